// round 13
// baseline (speedup 1.0000x reference)
#include <cuda_runtime.h>
#include <cstdint>

#define BB 2048
#define C_IN 256
#define L_IN 256
#define C_OUT 64
#define KW 16
#define L_OUT 61
#define FLAT 3904    // 64*61
#define FLAT2 1952   // FLAT/2 (f16x2 pairs)
#define H1 512
#define H12 256      // H1/2 pairs
#define H2 128
#define KTOT 4096    // C_IN*KW
#define NCHUNK 64    // conv K chunks of 64 (4 ci each)

// ---------------- scratch (static device arrays; no allocation) -------------
__device__ unsigned g_acth[(size_t)BB * FLAT2];   // act fp16x2, [b][(l*64+co)/2]
__device__ unsigned g_w12h[H2 * FLAT2];           // W12 fp16x2, [j][(l*64+co)/2]
__device__ float    g_b12[H2];
__device__ float    g_cb[C_OUT];
__device__ unsigned g_wh[C_OUT * (KTOT / 2)];     // conv weights fp16x2, [co][K/2]
__device__ unsigned g_f1h[(size_t)FLAT * H12];    // fc1^T fp16x2, [f][h/2]
__device__ unsigned g_f2h[H2 * H12];              // fc2 fp16x2, [j][h/2]

// ---------------- PTX helpers ----------------------------------------------
__device__ __forceinline__ uint32_t smem_u32(const void* p) {
    uint32_t a;
    asm("{ .reg .u64 t; cvta.to.shared.u64 t, %1; cvt.u32.u64 %0, t; }"
        : "=r"(a) : "l"(p));
    return a;
}
__device__ __forceinline__ uint32_t f16pair(float lo, float hi) {
    uint32_t r;
    asm("cvt.rn.f16x2.f32 %0, %1, %2;" : "=r"(r) : "f"(hi), "f"(lo));
    return r;
}
__device__ __forceinline__ unsigned short f16one(float v) {
    unsigned short r;
    asm("cvt.rn.f16.f32 %0, %1;" : "=h"(r) : "f"(v));
    return r;
}
__device__ __forceinline__ uint32_t lds32(uint32_t addr) {
    uint32_t v;
    asm volatile("ld.shared.b32 %0, [%1];" : "=r"(v) : "r"(addr));
    return v;
}
__device__ __forceinline__ void sts64(uint32_t addr, uint32_t v0, uint32_t v1) {
    asm volatile("st.shared.v2.b32 [%0], {%1, %2};" :: "r"(addr), "r"(v0), "r"(v1));
}
__device__ __forceinline__ void ldsm4(uint32_t* r, uint32_t addr) {
    asm volatile("ldmatrix.sync.aligned.m8n8.x4.shared.b16 {%0,%1,%2,%3}, [%4];"
                 : "=r"(r[0]), "=r"(r[1]), "=r"(r[2]), "=r"(r[3]) : "r"(addr));
}
__device__ __forceinline__ void hmma(float* d, uint32_t a0, uint32_t a1,
                                     uint32_t a2, uint32_t a3,
                                     uint32_t b0, uint32_t b1) {
    asm volatile("mma.sync.aligned.m16n8k16.row.col.f32.f16.f16.f32 "
                 "{%0,%1,%2,%3}, {%4,%5,%6,%7}, {%8,%9}, {%0,%1,%2,%3};"
                 : "+f"(d[0]), "+f"(d[1]), "+f"(d[2]), "+f"(d[3])
                 : "r"(a0), "r"(a1), "r"(a2), "r"(a3), "r"(b0), "r"(b1));
}
#define CP_ASYNC16(dst, src) \
    asm volatile("cp.async.cg.shared.global [%0], [%1], 16;" \
                 :: "r"(dst), "l"(src) : "memory")
#define CP_COMMIT() asm volatile("cp.async.commit_group;" ::: "memory")
#define CP_WAIT0()  asm volatile("cp.async.wait_group 0;" ::: "memory")

// ---------------------------------------------------------------------------
// prep_all: one launch for all weight preprocessing.
// ---------------------------------------------------------------------------
__global__ void __launch_bounds__(256) prep_all_kernel(
        const float* __restrict__ conv_w, const float* __restrict__ conv_b,
        const float* __restrict__ gamma,  const float* __restrict__ beta,
        const float* __restrict__ mean,   const float* __restrict__ var,
        const float* __restrict__ fc1_b,  const float* __restrict__ fc2_w,
        const float* __restrict__ fc2_b) {
    int bid = blockIdx.x, t = threadIdx.x;
    if (bid < 512) {
        int idx = bid * 256 + t;              // exactly C_OUT*(KTOT/2)
        int co = idx >> 11;
        int kg = (idx & 2047) * 2;
        int ci = kg >> 4, k = kg & 15;
        float inv = gamma[co] * rsqrtf(var[co] + 1e-5f);
        const float* src = conv_w + ((size_t)co * C_IN + ci) * KW + k;
        g_wh[idx] = f16pair(src[0] * inv, src[1] * inv);
    } else if (bid < 640) {
        int idx = (bid - 512) * 256 + t;      // exactly H2*H12
        g_f2h[idx] = f16pair(fc2_w[2 * idx], fc2_w[2 * idx + 1]);
    } else {
        if (t < H2) {
            float s = fc2_b[t];
            for (int h = 0; h < H1; h++) s = fmaf(fc2_w[t * H1 + h], fc1_b[h], s);
            g_b12[t] = s;
        } else if (t < H2 + C_OUT) {
            int co = t - H2;
            float inv = gamma[co] * rsqrtf(var[co] + 1e-5f);
            g_cb[co] = (conv_b[co] - mean[co]) * inv + beta[co];
        }
    }
}

// ---------------------------------------------------------------------------
// fc1 transpose + cvt: [h=512][f=3904] fp32 -> g_f1h [f][h/2] fp16x2.
// ---------------------------------------------------------------------------
__global__ void __launch_bounds__(256) f1t_kernel(const float* __restrict__ fc1_w) {
    __shared__ float s[64][33];
    int t  = threadIdx.x;
    int f0 = blockIdx.x * 32;
    int h0 = blockIdx.y * 64;
#pragma unroll
    for (int it = 0; it < 8; it++) {
        int idx = it * 256 + t;
        int hh = idx >> 5, ff = idx & 31;
        s[hh][ff] = fc1_w[(size_t)(h0 + hh) * FLAT + f0 + ff];
    }
    __syncthreads();
    int hb2 = blockIdx.y * 32;
#pragma unroll
    for (int it = 0; it < 4; it++) {
        int idx = it * 256 + t;
        int ff = idx >> 5, pi = idx & 31;
        g_f1h[(size_t)(f0 + ff) * H12 + hb2 + pi] =
            f16pair(s[2 * pi][ff], s[2 * pi + 1][ff]);
    }
}

// ---------------------------------------------------------------------------
// W12 = fc2 @ fc1 via mma.sync. M=128 j, N=32 f per block (grid 122), K=512.
// ---------------------------------------------------------------------------
__global__ void __launch_bounds__(256) w12mma_kernel() {
    __shared__ uint32_t asm_[H2 * 32];
    __shared__ uint32_t bsm_[32 * 32];

    int t = threadIdx.x, w = t >> 5, lane = t & 31;
    int mw = w;
    uint32_t as_addr = smem_u32(asm_);
    uint32_t bs_addr = smem_u32(bsm_);
    int f0 = blockIdx.x * 32;

    float acc[4][4];
#pragma unroll
    for (int nt = 0; nt < 4; nt++)
#pragma unroll
        for (int r = 0; r < 4; r++) acc[nt][r] = 0.f;

    int sub = lane >> 3, r8 = lane & 7;
    int arow = mw * 16 + (sub & 1) * 8 + r8;
    uint32_t akb   = (uint32_t)((sub >> 1) * 16);
    uint32_t abase = as_addr + (uint32_t)(arow * 128);
    uint32_t aswz  = (uint32_t)(r8 << 4);

    int btile = lane >> 3, brow = lane & 7;
    uint32_t bbase[2];
    uint32_t bkb  = (uint32_t)((btile & 1) * 16);
    uint32_t bswz = (uint32_t)(brow << 4);
#pragma unroll
    for (int p = 0; p < 2; p++) {
        int floc = (2 * p + (btile >> 1)) * 8 + brow;
        bbase[p] = bs_addr + (uint32_t)(floc * 128);
    }

    int wj = t >> 1, wh = t & 1;
    char* arowp = (char*)asm_ + wj * 128;
    uint32_t awz = (uint32_t)((wj & 7) << 4);
    int am = t >> 3, akg = t & 7;
    uint32_t bst = bs_addr + (uint32_t)(am * 128) +
                   (((uint32_t)(akg * 16)) ^ ((uint32_t)((am & 7) << 4)));

#pragma unroll 1
    for (int cc = 0; cc < 8; cc++) {
        __syncthreads();
        {
            const uint4* src = (const uint4*)(g_f2h + (size_t)wj * H12 + cc * 32 + wh * 16);
#pragma unroll
            for (int qq = 0; qq < 4; qq++) {
                uint4 v = src[qq];
                *(uint4*)(arowp + (((uint32_t)(wh * 64 + qq * 16)) ^ awz)) = v;
            }
        }
        {
            uint4 v = *(const uint4*)(g_f1h + (size_t)(f0 + am) * H12 + cc * 32 + akg * 4);
            *(uint4*)((char*)bsm_ + (bst - bs_addr)) = v;
        }
        __syncthreads();

#pragma unroll
        for (int ks = 0; ks < 4; ks++) {
            uint32_t af[4];
            ldsm4(af, abase + (((uint32_t)(ks * 32) + akb) ^ aswz));
            uint32_t bf[8];
#pragma unroll
            for (int p = 0; p < 2; p++)
                ldsm4(&bf[4 * p], bbase[p] + (((uint32_t)(ks * 32) + bkb) ^ bswz));
#pragma unroll
            for (int nt = 0; nt < 4; nt++) {
                int bi = 4 * (nt >> 1) + 2 * (nt & 1);
                hmma(acc[nt], af[0], af[1], af[2], af[3], bf[bi], bf[bi + 1]);
            }
        }
    }

    unsigned short* dst = (unsigned short*)g_w12h;
    int r = lane >> 2, c = lane & 3;
#pragma unroll
    for (int nt = 0; nt < 4; nt++) {
#pragma unroll
        for (int e = 0; e < 4; e++) {
            int f = f0 + nt * 8 + 2 * c + (e & 1);
            int j = mw * 16 + r + (e >> 1) * 8;
            int co = f / L_OUT;
            int l  = f - co * L_OUT;
            dst[(size_t)j * FLAT + l * 64 + co] = f16one(acc[nt][e]);
        }
    }
}

// ---------------------------------------------------------------------------
// Conv + BN + ReLU via mma.sync. Single-sync double-buffered pipeline:
// per chunk: wait0+sync -> issue LDG x(cc+1) + cp.async B(cc+1) -> compute(cc)
// -> STS x(cc+1). 64 barriers total; staging latency hidden behind compute.
// Block: 256 thr / 8 warps, 4 batches (grid 512). Warp = batch x l-half,
// M=32 per warp x all 64 co.
// ---------------------------------------------------------------------------
__global__ void __launch_bounds__(256, 2) conv_mma_kernel(const float* __restrict__ x) {
    __shared__ unsigned xh[2][16 * 128];     // fp16x2 x, 2 x 8KB
    __shared__ uint32_t bsm[2][C_OUT * 32];  // fp16x2 weights swizzled, 2 x 8KB

    int t = threadIdx.x, w = t >> 5, lane = t & 31;
    int q = w >> 1, half = w & 1;
    uint32_t xh_addr = smem_u32(xh);
    uint32_t bs_addr = smem_u32(bsm);

    float acc[2][8][4];
#pragma unroll
    for (int mt = 0; mt < 2; mt++)
#pragma unroll
        for (int nt = 0; nt < 8; nt++)
#pragma unroll
            for (int r = 0; r < 4; r++) acc[mt][nt][r] = 0.f;

    // ---- B ldmatrix addressing (within-buffer offsets) ----
    int btile = lane >> 3, brow = lane & 7;
    uint32_t bbase[4], bkb[4], bsw[4];
#pragma unroll
    for (int p = 0; p < 4; p++) {
        int co = (2 * p + (btile >> 1)) * 8 + brow;
        bbase[p] = (uint32_t)(co * 128);
        bkb[p]   = (uint32_t)((btile & 1) * 16);
        bsw[p]   = (uint32_t)((co & 7) << 4);
    }

    // ---- A addressing: byte offset within (q,ks) fp16 row (512B) ----
    int c = lane & 3, rq = lane >> 2;
    int lbase = half * 32;
    uint32_t aoff = (uint32_t)(8 * (lbase + rq) + 4 * c);

    // ---- x staging: thread owns row r=(t>>4), quarter lane16=t&15 ----
    int xr = t >> 4, lane16 = t & 15;
    int xq = xr >> 2, xci = xr & 3;
    const float4* xsrc = (const float4*)x
        + ((size_t)(blockIdx.x * 4 + xq) * (C_IN * L_IN) + xci * L_IN) / 4 + lane16;
    uint32_t xsts = xh_addr + (uint32_t)(xr * 512 + lane16 * 8);

    // ---- B staging via cp.async ----
    int brw = t >> 3;
    int bg  = t & 7;
    uint32_t bd0 = bs_addr + (uint32_t)(brw * 128) + (((uint32_t)(bg * 16)) ^ ((uint32_t)((brw & 7) << 4)));
    uint32_t bd1 = bs_addr + (uint32_t)((brw + 32) * 128) + (((uint32_t)(bg * 16)) ^ ((uint32_t)(((brw + 32) & 7) << 4)));
    const char* bsrc0 = (const char*)g_wh + (size_t)brw * 8192 + bg * 16;
    const char* bsrc1 = bsrc0 + (size_t)32 * 8192;

    // ---- prologue: chunk 0 fully staged before the loop's first sync ----
    float4 rx0 = xsrc[0], rx1 = xsrc[16], rx2 = xsrc[32], rx3 = xsrc[48];
    sts64(xsts,       f16pair(rx0.x, rx0.y), f16pair(rx0.z, rx0.w));
    sts64(xsts + 128, f16pair(rx1.x, rx1.y), f16pair(rx1.z, rx1.w));
    sts64(xsts + 256, f16pair(rx2.x, rx2.y), f16pair(rx2.z, rx2.w));
    sts64(xsts + 384, f16pair(rx3.x, rx3.y), f16pair(rx3.z, rx3.w));
    CP_ASYNC16(bd0, bsrc0);
    CP_ASYNC16(bd1, bsrc1);
    CP_COMMIT();

#pragma unroll 1
    for (int cc = 0; cc < NCHUNK; cc++) {
        CP_WAIT0();                            // B(cc) landed (this thread)
        __syncthreads();                       // all threads: B(cc)+x(cc) visible;
                                               // everyone done computing cc-1
        if (cc < NCHUNK - 1) {                 // issue next chunk's loads now
            const float4* nsrc = xsrc + (size_t)(cc + 1) * 256;
            rx0 = nsrc[0]; rx1 = nsrc[16]; rx2 = nsrc[32]; rx3 = nsrc[48];
            uint32_t bb = (uint32_t)(((cc + 1) & 1) * (C_OUT * 32 * 4));
            size_t bo = (size_t)(cc + 1) * 128;
            CP_ASYNC16(bd0 + bb, bsrc0 + bo);
            CP_ASYNC16(bd1 + bb, bsrc1 + bo);
            CP_COMMIT();
        }

        int buf = cc & 1;
        uint32_t bbuf = bs_addr + (uint32_t)(buf * (C_OUT * 32 * 4));
        uint32_t xchunk = xh_addr + (uint32_t)(buf * 8192) + (uint32_t)(q * 4 * 512);

#pragma unroll
        for (int ks = 0; ks < 4; ks++) {
            uint32_t bfr[16];
#pragma unroll
            for (int p = 0; p < 4; p++) {
                uint32_t addr = bbuf + bbase[p] + (((uint32_t)(ks * 32) + bkb[p]) ^ bsw[p]);
                ldsm4(&bfr[4 * p], addr);
            }
            uint32_t xrow = xchunk + (uint32_t)(ks * 512) + aoff;
#pragma unroll
            for (int mt = 0; mt < 2; mt++) {
                uint32_t base = xrow + (uint32_t)(mt * 128);
                uint32_t a0 = lds32(base);
                uint32_t a1 = lds32(base + 64);
                uint32_t a2 = lds32(base + 16);
                uint32_t a3 = lds32(base + 80);
#pragma unroll
                for (int nt = 0; nt < 8; nt++) {
                    int bi = 4 * (nt >> 1) + 2 * (nt & 1);
                    hmma(acc[mt][nt], a0, a1, a2, a3, bfr[bi], bfr[bi + 1]);
                }
            }
        }

        if (cc < NCHUNK - 1) {                 // LDG long done; convert+store
            uint32_t xb = xsts + (uint32_t)(((cc + 1) & 1) * 8192);
            sts64(xb,       f16pair(rx0.x, rx0.y), f16pair(rx0.z, rx0.w));
            sts64(xb + 128, f16pair(rx1.x, rx1.y), f16pair(rx1.z, rx1.w));
            sts64(xb + 256, f16pair(rx2.x, rx2.y), f16pair(rx2.z, rx2.w));
            sts64(xb + 384, f16pair(rx3.x, rx3.y), f16pair(rx3.z, rx3.w));
        }
    }

    // ---- epilogue: bias + relu -> fp16 pairs -> g_acth[b][(l*64+co)/2] ----
    int b = blockIdx.x * 4 + q;
    unsigned* dst = g_acth + (size_t)b * FLAT2;
#pragma unroll
    for (int mt = 0; mt < 2; mt++) {
        int l1 = lbase + mt * 16 + rq;
        int l2 = l1 + 8;
#pragma unroll
        for (int nt = 0; nt < 8; nt++) {
            int co0 = nt * 8 + 2 * c;
            float cb0 = g_cb[co0], cb1 = g_cb[co0 + 1];
            if (l1 < L_OUT) {
                float v0 = acc[mt][nt][0] + cb0;
                float v1 = acc[mt][nt][1] + cb1;
                dst[l1 * 32 + nt * 4 + c] = f16pair(v0 > 0.f ? v0 : 0.f, v1 > 0.f ? v1 : 0.f);
            }
            if (l2 < L_OUT) {
                float v2 = acc[mt][nt][2] + cb0;
                float v3 = acc[mt][nt][3] + cb1;
                dst[l2 * 32 + nt * 4 + c] = f16pair(v2 > 0.f ? v2 : 0.f, v3 > 0.f ? v3 : 0.f);
            }
        }
    }
}

// ---------------------------------------------------------------------------
// feats = act @ W12^T + b12 via mma.sync, fused parabit heads -> out.
// Now fully cp.async double-buffered (A and B), single sync per chunk.
// M=16 batches per block (grid 128). Warp w -> j-slice [w*16, w*16+16).
// ---------------------------------------------------------------------------
__global__ void __launch_bounds__(256) feats_mma_kernel(const float* __restrict__ bit_w,
                                                        const float* __restrict__ bit_b,
                                                        float* __restrict__ out) {
    __shared__ uint32_t as_[2][16 * 32];     // A tiles, 2 x 2KB
    __shared__ uint32_t ws_[2][H2 * 32];     // B tiles, 2 x 16KB
    __shared__ float sb12[H2], sbw[H2 * 2], sbb[H2 * 2];

    int t = threadIdx.x, w = t >> 5, lane = t & 31;
    if (t < H2) sb12[t] = g_b12[t];
    if (t < H2 * 2) { sbw[t] = bit_w[t]; sbb[t] = bit_b[t]; }
    uint32_t as_addr = smem_u32(as_);
    uint32_t ws_addr = smem_u32(ws_);

    int b0 = blockIdx.x * 16;

    float acc[2][4];
#pragma unroll
    for (int nt = 0; nt < 2; nt++)
#pragma unroll
        for (int r = 0; r < 4; r++) acc[nt][r] = 0.f;

    // A frag addressing (within buffer 0)
    int sub = lane >> 3, r8 = lane & 7;
    int arow = (sub & 1) * 8 + r8;
    uint32_t akb   = (uint32_t)((sub >> 1) * 16);
    uint32_t abase = as_addr + (uint32_t)(arow * 128);
    uint32_t aswz  = (uint32_t)(r8 << 4);

    // B frag addressing (within buffer 0)
    int g = lane >> 3, brow = lane & 7;
    int bj  = w * 16 + (g >> 1) * 8 + brow;
    uint32_t bkb  = (uint32_t)((g & 1) * 16);
    uint32_t bbase = ws_addr + (uint32_t)(bj * 128);
    uint32_t bswz = (uint32_t)(brow << 4);

    // A staging: threads t<128, one 16B cp.async each (row am, group akg)
    int am = t >> 3, akg = t & 7;            // am 0..31; only am<16 used
    uint32_t adst = as_addr + (uint32_t)(am * 128) +
                    (((uint32_t)(akg * 16)) ^ ((uint32_t)((am & 7) << 4)));
    const char* asrc = (const char*)g_acth + ((size_t)(b0 + am) * FLAT2) * 4 + akg * 16;

    // B staging: all threads, 4 x 16B cp.async each (row wj, half wh)
    int wj = t >> 1, wh = t & 1;
    uint32_t wswz = (uint32_t)((wj & 7) << 4);
    uint32_t bdst[4];
#pragma unroll
    for (int qq = 0; qq < 4; qq++)
        bdst[qq] = ws_addr + (uint32_t)(wj * 128) +
                   (((uint32_t)(wh * 64 + qq * 16)) ^ wswz);
    const char* bsrcB = (const char*)g_w12h + ((size_t)wj * FLAT2) * 4 + wh * 64;

#define FSTAGE(cc, buf) do {                                                   \
    uint32_t ab = (uint32_t)((buf) * 2048);                                    \
    uint32_t wb = (uint32_t)((buf) * 16384);                                   \
    size_t off = (size_t)(cc) * 128;                                           \
    if (am < 16) CP_ASYNC16(adst + ab, asrc + off);                            \
    CP_ASYNC16(bdst[0] + wb, bsrcB + off);                                     \
    CP_ASYNC16(bdst[1] + wb, bsrcB + off + 16);                                \
    CP_ASYNC16(bdst[2] + wb, bsrcB + off + 32);                                \
    CP_ASYNC16(bdst[3] + wb, bsrcB + off + 48);                                \
} while (0)

    FSTAGE(0, 0);
    CP_COMMIT();

#pragma unroll 1
    for (int cc = 0; cc < 61; cc++) {
        CP_WAIT0();
        __syncthreads();
        if (cc < 60) {
            FSTAGE(cc + 1, (cc + 1) & 1);
            CP_COMMIT();
        }
        int buf = cc & 1;
        uint32_t ao = (uint32_t)(buf * 2048);
        uint32_t wo = (uint32_t)(buf * 16384);
#pragma unroll
        for (int ks = 0; ks < 4; ks++) {
            uint32_t af[4];
            ldsm4(af, abase + ao + (((uint32_t)(ks * 32) + akb) ^ aswz));
            uint32_t bf[4];
            ldsm4(bf, bbase + wo + (((uint32_t)(ks * 32) + bkb) ^ bswz));
#pragma unroll
            for (int nt = 0; nt < 2; nt++)
                hmma(acc[nt], af[0], af[1], af[2], af[3], bf[2 * nt], bf[2 * nt + 1]);
        }
    }
#undef FSTAGE

    // ---- epilogue: + b12, parabit heads, write out ----
    int r = lane >> 2, c = lane & 3;
#pragma unroll
    for (int nt = 0; nt < 2; nt++) {
        int j0 = w * 16 + nt * 8 + 2 * c;
        float bj0 = sb12[j0], bj1 = sb12[j0 + 1];
        float bw00 = sbw[j0 * 2], bw01 = sbw[j0 * 2 + 1];
        float bw10 = sbw[j0 * 2 + 2], bw11 = sbw[j0 * 2 + 3];
        float bb00 = sbb[j0 * 2], bb01 = sbb[j0 * 2 + 1];
        float bb10 = sbb[j0 * 2 + 2], bb11 = sbb[j0 * 2 + 3];
        {
            int b = b0 + r;
            float f0 = acc[nt][0] + bj0;
            float f1 = acc[nt][1] + bj1;
            float4 o = make_float4(fmaf(f0, bw00, bb00), fmaf(f0, bw01, bb01),
                                   fmaf(f1, bw10, bb10), fmaf(f1, bw11, bb11));
            *(float4*)(out + ((size_t)b * H2 + j0) * 2) = o;
        }
        {
            int b = b0 + r + 8;
            float f2 = acc[nt][2] + bj0;
            float f3 = acc[nt][3] + bj1;
            float4 o = make_float4(fmaf(f2, bw00, bb00), fmaf(f2, bw01, bb01),
                                   fmaf(f3, bw10, bb10), fmaf(f3, bw11, bb11));
            *(float4*)(out + ((size_t)b * H2 + j0) * 2) = o;
        }
    }
}

// ---------------------------------------------------------------------------
extern "C" void kernel_launch(void* const* d_in, const int* in_sizes, int n_in,
                              void* d_out, int out_size) {
    const float* x      = (const float*)d_in[0];
    const float* conv_w = (const float*)d_in[1];
    const float* conv_b = (const float*)d_in[2];
    const float* gamma  = (const float*)d_in[3];
    const float* beta   = (const float*)d_in[4];
    const float* mean   = (const float*)d_in[5];
    const float* var    = (const float*)d_in[6];
    const float* fc1_w  = (const float*)d_in[7];
    const float* fc1_b  = (const float*)d_in[8];
    const float* fc2_w  = (const float*)d_in[9];
    const float* fc2_b  = (const float*)d_in[10];
    const float* bit_w  = (const float*)d_in[11];
    const float* bit_b  = (const float*)d_in[12];
    float* out = (float*)d_out;

    static cudaStream_t s2 = nullptr;
    static cudaEvent_t evFork = nullptr, evJoin = nullptr;
    if (!s2) {
        cudaStreamCreateWithFlags(&s2, cudaStreamNonBlocking);
        cudaEventCreateWithFlags(&evFork, cudaEventDisableTiming);
        cudaEventCreateWithFlags(&evJoin, cudaEventDisableTiming);
    }

    // main stream: prep_all -> conv  |  s2: f1t -> w12mma (parallel to conv)
    prep_all_kernel<<<641, 256>>>(conv_w, conv_b, gamma, beta, mean, var,
                                  fc1_b, fc2_w, fc2_b);
    cudaEventRecord(evFork, 0);
    cudaStreamWaitEvent(s2, evFork, 0);
    f1t_kernel<<<dim3(FLAT / 32, 8), 256, 0, s2>>>(fc1_w);
    w12mma_kernel<<<FLAT / 32, 256, 0, s2>>>();
    cudaEventRecord(evJoin, s2);

    conv_mma_kernel<<<BB / 4, 256>>>(x);
    cudaStreamWaitEvent((cudaStream_t)0, evJoin, 0);
    feats_mma_kernel<<<BB / 16, 256>>>(bit_w, bit_b, out);
}

// round 15
// speedup vs baseline: 1.2451x; 1.2451x over previous
#include <cuda_runtime.h>
#include <cstdint>

#define BB 2048
#define C_IN 256
#define L_IN 256
#define C_OUT 64
#define KW 16
#define L_OUT 61
#define FLAT 3904    // 64*61
#define FLAT2 1952   // FLAT/2 (f16x2 pairs)
#define H1 512
#define H12 256      // H1/2 pairs
#define H2 128
#define KTOT 4096    // C_IN*KW
#define NCHUNK 64    // conv K chunks of 64 (4 ci each)

// ---------------- scratch (static device arrays; no allocation) -------------
__device__ unsigned g_acth[(size_t)BB * FLAT2];   // act fp16x2, [b][(l*64+co)/2]
__device__ unsigned g_w12h[H2 * FLAT2];           // W12 fp16x2, [j][(l*64+co)/2]
__device__ float    g_b12[H2];
__device__ float    g_cb[C_OUT];
__device__ unsigned g_wh[C_OUT * (KTOT / 2)];     // conv weights fp16x2, [co][K/2]
__device__ unsigned g_f1h[(size_t)FLAT * H12];    // fc1^T fp16x2, [f][h/2]
__device__ unsigned g_f2h[H2 * H12];              // fc2 fp16x2, [j][h/2]

// ---------------- PTX helpers ----------------------------------------------
__device__ __forceinline__ uint32_t smem_u32(const void* p) {
    uint32_t a;
    asm("{ .reg .u64 t; cvta.to.shared.u64 t, %1; cvt.u32.u64 %0, t; }"
        : "=r"(a) : "l"(p));
    return a;
}
__device__ __forceinline__ uint32_t f16pair(float lo, float hi) {
    uint32_t r;
    asm("cvt.rn.f16x2.f32 %0, %1, %2;" : "=r"(r) : "f"(hi), "f"(lo));
    return r;
}
__device__ __forceinline__ unsigned short f16one(float v) {
    unsigned short r;
    asm("cvt.rn.f16.f32 %0, %1;" : "=h"(r) : "f"(v));
    return r;
}
__device__ __forceinline__ uint32_t lds32(uint32_t addr) {
    uint32_t v;
    asm volatile("ld.shared.b32 %0, [%1];" : "=r"(v) : "r"(addr));
    return v;
}
__device__ __forceinline__ void sts64(uint32_t addr, uint32_t v0, uint32_t v1) {
    asm volatile("st.shared.v2.b32 [%0], {%1, %2};" :: "r"(addr), "r"(v0), "r"(v1));
}
__device__ __forceinline__ void ldsm4(uint32_t* r, uint32_t addr) {
    asm volatile("ldmatrix.sync.aligned.m8n8.x4.shared.b16 {%0,%1,%2,%3}, [%4];"
                 : "=r"(r[0]), "=r"(r[1]), "=r"(r[2]), "=r"(r[3]) : "r"(addr));
}
__device__ __forceinline__ void hmma(float* d, uint32_t a0, uint32_t a1,
                                     uint32_t a2, uint32_t a3,
                                     uint32_t b0, uint32_t b1) {
    asm volatile("mma.sync.aligned.m16n8k16.row.col.f32.f16.f16.f32 "
                 "{%0,%1,%2,%3}, {%4,%5,%6,%7}, {%8,%9}, {%0,%1,%2,%3};"
                 : "+f"(d[0]), "+f"(d[1]), "+f"(d[2]), "+f"(d[3])
                 : "r"(a0), "r"(a1), "r"(a2), "r"(a3), "r"(b0), "r"(b1));
}
#define CP_ASYNC16(dst, src) \
    asm volatile("cp.async.cg.shared.global [%0], [%1], 16;" \
                 :: "r"(dst), "l"(src) : "memory")
#define CP_COMMIT() asm volatile("cp.async.commit_group;" ::: "memory")
#define CP_WAIT1()  asm volatile("cp.async.wait_group 1;" ::: "memory")

// ---------------------------------------------------------------------------
// prep_all: one launch for all weight preprocessing.
// ---------------------------------------------------------------------------
__global__ void __launch_bounds__(256) prep_all_kernel(
        const float* __restrict__ conv_w, const float* __restrict__ conv_b,
        const float* __restrict__ gamma,  const float* __restrict__ beta,
        const float* __restrict__ mean,   const float* __restrict__ var,
        const float* __restrict__ fc1_b,  const float* __restrict__ fc2_w,
        const float* __restrict__ fc2_b) {
    int bid = blockIdx.x, t = threadIdx.x;
    if (bid < 512) {
        int idx = bid * 256 + t;              // exactly C_OUT*(KTOT/2)
        int co = idx >> 11;
        int kg = (idx & 2047) * 2;
        int ci = kg >> 4, k = kg & 15;
        float inv = gamma[co] * rsqrtf(var[co] + 1e-5f);
        const float* src = conv_w + ((size_t)co * C_IN + ci) * KW + k;
        g_wh[idx] = f16pair(src[0] * inv, src[1] * inv);
    } else if (bid < 640) {
        int idx = (bid - 512) * 256 + t;      // exactly H2*H12
        g_f2h[idx] = f16pair(fc2_w[2 * idx], fc2_w[2 * idx + 1]);
    } else {
        if (t < H2) {
            float s = fc2_b[t];
            for (int h = 0; h < H1; h++) s = fmaf(fc2_w[t * H1 + h], fc1_b[h], s);
            g_b12[t] = s;
        } else if (t < H2 + C_OUT) {
            int co = t - H2;
            float inv = gamma[co] * rsqrtf(var[co] + 1e-5f);
            g_cb[co] = (conv_b[co] - mean[co]) * inv + beta[co];
        }
    }
}

// ---------------------------------------------------------------------------
// fc1 transpose + cvt: [h=512][f=3904] fp32 -> g_f1h [f][h/2] fp16x2.
// ---------------------------------------------------------------------------
__global__ void __launch_bounds__(256) f1t_kernel(const float* __restrict__ fc1_w) {
    __shared__ float s[64][33];
    int t  = threadIdx.x;
    int f0 = blockIdx.x * 32;
    int h0 = blockIdx.y * 64;
#pragma unroll
    for (int it = 0; it < 8; it++) {
        int idx = it * 256 + t;
        int hh = idx >> 5, ff = idx & 31;
        s[hh][ff] = fc1_w[(size_t)(h0 + hh) * FLAT + f0 + ff];
    }
    __syncthreads();
    int hb2 = blockIdx.y * 32;
#pragma unroll
    for (int it = 0; it < 4; it++) {
        int idx = it * 256 + t;
        int ff = idx >> 5, pi = idx & 31;
        g_f1h[(size_t)(f0 + ff) * H12 + hb2 + pi] =
            f16pair(s[2 * pi][ff], s[2 * pi + 1][ff]);
    }
}

// ---------------------------------------------------------------------------
// W12 = fc2 @ fc1 via mma.sync. M=128 j, N=32 f per block (grid 122), K=512.
// ---------------------------------------------------------------------------
__global__ void __launch_bounds__(256) w12mma_kernel() {
    __shared__ uint32_t asm_[H2 * 32];
    __shared__ uint32_t bsm_[32 * 32];

    int t = threadIdx.x, w = t >> 5, lane = t & 31;
    int mw = w;
    uint32_t as_addr = smem_u32(asm_);
    uint32_t bs_addr = smem_u32(bsm_);
    int f0 = blockIdx.x * 32;

    float acc[4][4];
#pragma unroll
    for (int nt = 0; nt < 4; nt++)
#pragma unroll
        for (int r = 0; r < 4; r++) acc[nt][r] = 0.f;

    int sub = lane >> 3, r8 = lane & 7;
    int arow = mw * 16 + (sub & 1) * 8 + r8;
    uint32_t akb   = (uint32_t)((sub >> 1) * 16);
    uint32_t abase = as_addr + (uint32_t)(arow * 128);
    uint32_t aswz  = (uint32_t)(r8 << 4);

    int btile = lane >> 3, brow = lane & 7;
    uint32_t bbase[2];
    uint32_t bkb  = (uint32_t)((btile & 1) * 16);
    uint32_t bswz = (uint32_t)(brow << 4);
#pragma unroll
    for (int p = 0; p < 2; p++) {
        int floc = (2 * p + (btile >> 1)) * 8 + brow;
        bbase[p] = bs_addr + (uint32_t)(floc * 128);
    }

    int wj = t >> 1, wh = t & 1;
    char* arowp = (char*)asm_ + wj * 128;
    uint32_t awz = (uint32_t)((wj & 7) << 4);
    int am = t >> 3, akg = t & 7;
    uint32_t bst = bs_addr + (uint32_t)(am * 128) +
                   (((uint32_t)(akg * 16)) ^ ((uint32_t)((am & 7) << 4)));

#pragma unroll 1
    for (int cc = 0; cc < 8; cc++) {
        __syncthreads();
        {
            const uint4* src = (const uint4*)(g_f2h + (size_t)wj * H12 + cc * 32 + wh * 16);
#pragma unroll
            for (int qq = 0; qq < 4; qq++) {
                uint4 v = src[qq];
                *(uint4*)(arowp + (((uint32_t)(wh * 64 + qq * 16)) ^ awz)) = v;
            }
        }
        {
            uint4 v = *(const uint4*)(g_f1h + (size_t)(f0 + am) * H12 + cc * 32 + akg * 4);
            *(uint4*)((char*)bsm_ + (bst - bs_addr)) = v;
        }
        __syncthreads();

#pragma unroll
        for (int ks = 0; ks < 4; ks++) {
            uint32_t af[4];
            ldsm4(af, abase + (((uint32_t)(ks * 32) + akb) ^ aswz));
            uint32_t bf[8];
#pragma unroll
            for (int p = 0; p < 2; p++)
                ldsm4(&bf[4 * p], bbase[p] + (((uint32_t)(ks * 32) + bkb) ^ bswz));
#pragma unroll
            for (int nt = 0; nt < 4; nt++) {
                int bi = 4 * (nt >> 1) + 2 * (nt & 1);
                hmma(acc[nt], af[0], af[1], af[2], af[3], bf[bi], bf[bi + 1]);
            }
        }
    }

    unsigned short* dst = (unsigned short*)g_w12h;
    int r = lane >> 2, c = lane & 3;
#pragma unroll
    for (int nt = 0; nt < 4; nt++) {
#pragma unroll
        for (int e = 0; e < 4; e++) {
            int f = f0 + nt * 8 + 2 * c + (e & 1);
            int j = mw * 16 + r + (e >> 1) * 8;
            int co = f / L_OUT;
            int l  = f - co * L_OUT;
            dst[(size_t)j * FLAT + l * 64 + co] = f16one(acc[nt][e]);
        }
    }
}

// ---------------------------------------------------------------------------
// Conv + BN + ReLU via mma.sync (R12 structure, byte-identical inner loop).
// blk_off: block-index offset for split launches.
// ---------------------------------------------------------------------------
__global__ void __launch_bounds__(256, 2) conv_mma_kernel(const float* __restrict__ x,
                                                          int blk_off) {
    __shared__ unsigned xh[2][16 * 128];     // fp16x2 x, 2 x 8KB
    __shared__ uint32_t bsm[2][C_OUT * 32];  // fp16x2 weights swizzled, 2 x 8KB

    int t = threadIdx.x, w = t >> 5, lane = t & 31;
    int q = w >> 1, half = w & 1;
    int blk = blk_off + blockIdx.x;
    uint32_t xh_addr = smem_u32(xh);
    uint32_t bs_addr = smem_u32(bsm);

    float acc[2][8][4];
#pragma unroll
    for (int mt = 0; mt < 2; mt++)
#pragma unroll
        for (int nt = 0; nt < 8; nt++)
#pragma unroll
            for (int r = 0; r < 4; r++) acc[mt][nt][r] = 0.f;

    int btile = lane >> 3, brow = lane & 7;
    uint32_t bbase[4], bkb[4], bsw[4];
#pragma unroll
    for (int p = 0; p < 4; p++) {
        int co = (2 * p + (btile >> 1)) * 8 + brow;
        bbase[p] = (uint32_t)(co * 128);
        bkb[p]   = (uint32_t)((btile & 1) * 16);
        bsw[p]   = (uint32_t)((co & 7) << 4);
    }

    int c = lane & 3, rq = lane >> 2;
    int lbase = half * 32;
    uint32_t aoff = (uint32_t)(8 * (lbase + rq) + 4 * c);

    int xr = t >> 4, lane16 = t & 15;
    int xq = xr >> 2, xci = xr & 3;
    const float4* xsrc = (const float4*)x
        + ((size_t)(blk * 4 + xq) * (C_IN * L_IN) + xci * L_IN) / 4 + lane16;
    uint32_t xsts = xh_addr + (uint32_t)(xr * 512 + lane16 * 8);

    int brw = t >> 3;
    int bg  = t & 7;
    uint32_t bd0 = bs_addr + (uint32_t)(brw * 128) + (((uint32_t)(bg * 16)) ^ ((uint32_t)((brw & 7) << 4)));
    uint32_t bd1 = bs_addr + (uint32_t)((brw + 32) * 128) + (((uint32_t)(bg * 16)) ^ ((uint32_t)(((brw + 32) & 7) << 4)));
    const char* bsrc0 = (const char*)g_wh + (size_t)brw * 8192 + bg * 16;
    const char* bsrc1 = bsrc0 + (size_t)32 * 8192;

    // preload chunk 0
    float4 rx0 = xsrc[0], rx1 = xsrc[16], rx2 = xsrc[32], rx3 = xsrc[48];
    CP_ASYNC16(bd0, bsrc0);
    CP_ASYNC16(bd1, bsrc1);
    CP_COMMIT();

#pragma unroll 1
    for (int cc = 0; cc < NCHUNK; cc++) {
        __syncthreads();                       // prior compute done; buffers free
        {
            uint32_t xb = xsts + (uint32_t)((cc & 1) * 8192);
            sts64(xb,        f16pair(rx0.x, rx0.y), f16pair(rx0.z, rx0.w));
            sts64(xb + 128,  f16pair(rx1.x, rx1.y), f16pair(rx1.z, rx1.w));
            sts64(xb + 256,  f16pair(rx2.x, rx2.y), f16pair(rx2.z, rx2.w));
            sts64(xb + 384,  f16pair(rx3.x, rx3.y), f16pair(rx3.z, rx3.w));
        }
        if (cc < NCHUNK - 1) {
            const float4* nsrc = xsrc + (size_t)(cc + 1) * 256;
            rx0 = nsrc[0]; rx1 = nsrc[16]; rx2 = nsrc[32]; rx3 = nsrc[48];
            uint32_t bb = (uint32_t)(((cc + 1) & 1) * (C_OUT * 32 * 4));
            size_t bo = (size_t)(cc + 1) * 128;
            CP_ASYNC16(bd0 + bb, bsrc0 + bo);
            CP_ASYNC16(bd1 + bb, bsrc1 + bo);
        }
        CP_COMMIT();
        CP_WAIT1();                            // B(cc) landed
        __syncthreads();                       // x stores visible to all warps

        int buf = cc & 1;
        uint32_t bbuf = bs_addr + (uint32_t)(buf * (C_OUT * 32 * 4));
        uint32_t xchunk = xh_addr + (uint32_t)(buf * 8192) + (uint32_t)(q * 4 * 512);

#pragma unroll
        for (int ks = 0; ks < 4; ks++) {
            uint32_t bfr[16];
#pragma unroll
            for (int p = 0; p < 4; p++) {
                uint32_t addr = bbuf + bbase[p] + (((uint32_t)(ks * 32) + bkb[p]) ^ bsw[p]);
                ldsm4(&bfr[4 * p], addr);
            }
            uint32_t xrow = xchunk + (uint32_t)(ks * 512) + aoff;
#pragma unroll
            for (int mt = 0; mt < 2; mt++) {
                uint32_t base = xrow + (uint32_t)(mt * 128);
                uint32_t a0 = lds32(base);
                uint32_t a1 = lds32(base + 64);
                uint32_t a2 = lds32(base + 16);
                uint32_t a3 = lds32(base + 80);
#pragma unroll
                for (int nt = 0; nt < 8; nt++) {
                    int bi = 4 * (nt >> 1) + 2 * (nt & 1);
                    hmma(acc[mt][nt], a0, a1, a2, a3, bfr[bi], bfr[bi + 1]);
                }
            }
        }
    }

    int b = blk * 4 + q;
    unsigned* dst = g_acth + (size_t)b * FLAT2;
#pragma unroll
    for (int mt = 0; mt < 2; mt++) {
        int l1 = lbase + mt * 16 + rq;
        int l2 = l1 + 8;
#pragma unroll
        for (int nt = 0; nt < 8; nt++) {
            int co0 = nt * 8 + 2 * c;
            float cb0 = g_cb[co0], cb1 = g_cb[co0 + 1];
            if (l1 < L_OUT) {
                float v0 = acc[mt][nt][0] + cb0;
                float v1 = acc[mt][nt][1] + cb1;
                dst[l1 * 32 + nt * 4 + c] = f16pair(v0 > 0.f ? v0 : 0.f, v1 > 0.f ? v1 : 0.f);
            }
            if (l2 < L_OUT) {
                float v2 = acc[mt][nt][2] + cb0;
                float v3 = acc[mt][nt][3] + cb1;
                dst[l2 * 32 + nt * 4 + c] = f16pair(v2 > 0.f ? v2 : 0.f, v3 > 0.f ? v3 : 0.f);
            }
        }
    }
}

// ---------------------------------------------------------------------------
// feats = act @ W12^T + b12 via mma.sync, fused parabit heads -> out.
// R12 structure. M=16 batches per block; blk_off for split launches.
// ---------------------------------------------------------------------------
__global__ void __launch_bounds__(256) feats_mma_kernel(const float* __restrict__ bit_w,
                                                        const float* __restrict__ bit_b,
                                                        float* __restrict__ out,
                                                        int blk_off) {
    __shared__ uint32_t as_[16 * 32];
    __shared__ uint32_t ws_[H2 * 32];
    __shared__ float sb12[H2], sbw[H2 * 2], sbb[H2 * 2];

    int t = threadIdx.x, w = t >> 5, lane = t & 31;
    if (t < H2) sb12[t] = g_b12[t];
    if (t < H2 * 2) { sbw[t] = bit_w[t]; sbb[t] = bit_b[t]; }
    uint32_t as_addr = smem_u32(as_);
    uint32_t ws_addr = smem_u32(ws_);

    int b0 = (blk_off + blockIdx.x) * 16;

    float acc[2][4];
#pragma unroll
    for (int nt = 0; nt < 2; nt++)
#pragma unroll
        for (int r = 0; r < 4; r++) acc[nt][r] = 0.f;

    int sub = lane >> 3, r8 = lane & 7;
    int arow = (sub & 1) * 8 + r8;
    uint32_t akb   = (uint32_t)((sub >> 1) * 16);
    uint32_t abase = as_addr + (uint32_t)(arow * 128);
    uint32_t aswz  = (uint32_t)(r8 << 4);

    int g = lane >> 3, brow = lane & 7;
    int bj  = w * 16 + (g >> 1) * 8 + brow;
    uint32_t bkb  = (uint32_t)((g & 1) * 16);
    uint32_t bbase = ws_addr + (uint32_t)(bj * 128);
    uint32_t bswz = (uint32_t)(brow << 4);

    int am = t >> 3, akg = t & 7;
    uint32_t ast = as_addr + (uint32_t)(am * 128) +
                   (((uint32_t)(akg * 16)) ^ ((uint32_t)((am & 7) << 4)));
    int wj = t >> 1, wh = t & 1;
    char* wrow = (char*)ws_ + wj * 128;
    uint32_t wswz = (uint32_t)((wj & 7) << 4);

#pragma unroll 1
    for (int cc = 0; cc < 61; cc++) {
        __syncthreads();
        if (am < 16) {
            uint4 v = *(const uint4*)(g_acth + (size_t)(b0 + am) * FLAT2 + cc * 32 + akg * 4);
            *(uint4*)((char*)as_ + (ast - as_addr)) = v;
        }
        {
            const uint4* src = (const uint4*)(g_w12h + (size_t)wj * FLAT2 + cc * 32 + wh * 16);
#pragma unroll
            for (int qq = 0; qq < 4; qq++) {
                uint4 v = src[qq];
                *(uint4*)(wrow + (((uint32_t)(wh * 64 + qq * 16)) ^ wswz)) = v;
            }
        }
        __syncthreads();

#pragma unroll
        for (int ks = 0; ks < 4; ks++) {
            uint32_t af[4];
            ldsm4(af, abase + (((uint32_t)(ks * 32) + akb) ^ aswz));
            uint32_t bf[4];
            ldsm4(bf, bbase + (((uint32_t)(ks * 32) + bkb) ^ bswz));
#pragma unroll
            for (int nt = 0; nt < 2; nt++)
                hmma(acc[nt], af[0], af[1], af[2], af[3], bf[2 * nt], bf[2 * nt + 1]);
        }
    }

    int r = lane >> 2, c = lane & 3;
#pragma unroll
    for (int nt = 0; nt < 2; nt++) {
        int j0 = w * 16 + nt * 8 + 2 * c;
        float bj0 = sb12[j0], bj1 = sb12[j0 + 1];
        float bw00 = sbw[j0 * 2], bw01 = sbw[j0 * 2 + 1];
        float bw10 = sbw[j0 * 2 + 2], bw11 = sbw[j0 * 2 + 3];
        float bb00 = sbb[j0 * 2], bb01 = sbb[j0 * 2 + 1];
        float bb10 = sbb[j0 * 2 + 2], bb11 = sbb[j0 * 2 + 3];
        {
            int b = b0 + r;
            float f0 = acc[nt][0] + bj0;
            float f1 = acc[nt][1] + bj1;
            float4 o = make_float4(fmaf(f0, bw00, bb00), fmaf(f0, bw01, bb01),
                                   fmaf(f1, bw10, bb10), fmaf(f1, bw11, bb11));
            *(float4*)(out + ((size_t)b * H2 + j0) * 2) = o;
        }
        {
            int b = b0 + r + 8;
            float f2 = acc[nt][2] + bj0;
            float f3 = acc[nt][3] + bj1;
            float4 o = make_float4(fmaf(f2, bw00, bb00), fmaf(f2, bw01, bb01),
                                   fmaf(f3, bw10, bb10), fmaf(f3, bw11, bb11));
            *(float4*)(out + ((size_t)b * H2 + j0) * 2) = o;
        }
    }
}

// ---------------------------------------------------------------------------
extern "C" void kernel_launch(void* const* d_in, const int* in_sizes, int n_in,
                              void* d_out, int out_size) {
    const float* x      = (const float*)d_in[0];
    const float* conv_w = (const float*)d_in[1];
    const float* conv_b = (const float*)d_in[2];
    const float* gamma  = (const float*)d_in[3];
    const float* beta   = (const float*)d_in[4];
    const float* mean   = (const float*)d_in[5];
    const float* var    = (const float*)d_in[6];
    const float* fc1_w  = (const float*)d_in[7];
    const float* fc1_b  = (const float*)d_in[8];
    const float* fc2_w  = (const float*)d_in[9];
    const float* fc2_b  = (const float*)d_in[10];
    const float* bit_w  = (const float*)d_in[11];
    const float* bit_b  = (const float*)d_in[12];
    float* out = (float*)d_out;

    static cudaStream_t s2 = nullptr, s3 = nullptr;
    static cudaEvent_t evFork = nullptr, evJoin = nullptr, evCa = nullptr, evFa = nullptr;
    if (!s2) {
        cudaStreamCreateWithFlags(&s2, cudaStreamNonBlocking);
        cudaStreamCreateWithFlags(&s3, cudaStreamNonBlocking);
        cudaEventCreateWithFlags(&evFork, cudaEventDisableTiming);
        cudaEventCreateWithFlags(&evJoin, cudaEventDisableTiming);
        cudaEventCreateWithFlags(&evCa, cudaEventDisableTiming);
        cudaEventCreateWithFlags(&evFa, cudaEventDisableTiming);
    }

    // stream0: prep_all -> conv_a -> conv_b -> feats_b -> (wait feats_a)
    // s2:      f1t -> w12mma                       (parallel to conv)
    // s3:      feats_a (needs conv_a + w12)        (parallel to conv_b)
    prep_all_kernel<<<641, 256>>>(conv_w, conv_b, gamma, beta, mean, var,
                                  fc1_b, fc2_w, fc2_b);
    cudaEventRecord(evFork, 0);
    cudaStreamWaitEvent(s2, evFork, 0);
    f1t_kernel<<<dim3(FLAT / 32, 8), 256, 0, s2>>>(fc1_w);
    w12mma_kernel<<<FLAT / 32, 256, 0, s2>>>();
    cudaEventRecord(evJoin, s2);

    conv_mma_kernel<<<BB / 8, 256>>>(x, 0);            // batches 0..1023
    cudaEventRecord(evCa, 0);

    cudaStreamWaitEvent(s3, evCa, 0);
    cudaStreamWaitEvent(s3, evJoin, 0);
    feats_mma_kernel<<<BB / 32, 256, 0, s3>>>(bit_w, bit_b, out, 0);      // b 0..1023
    cudaEventRecord(evFa, s3);

    conv_mma_kernel<<<BB / 8, 256>>>(x, BB / 8);       // batches 1024..2047
    cudaStreamWaitEvent((cudaStream_t)0, evJoin, 0);
    feats_mma_kernel<<<BB / 32, 256>>>(bit_w, bit_b, out, BB / 32);       // b 1024..2047
    cudaStreamWaitEvent((cudaStream_t)0, evFa, 0);
}

// round 16
// speedup vs baseline: 1.5560x; 1.2497x over previous
#include <cuda_runtime.h>
#include <cstdint>

#define BB 2048
#define C_IN 256
#define L_IN 256
#define C_OUT 64
#define KW 16
#define L_OUT 61
#define FLAT 3904    // 64*61
#define FLAT2 1952   // FLAT/2 (f16x2 pairs)
#define H1 512
#define H12 256      // H1/2 pairs
#define H2 128
#define KTOT 4096    // C_IN*KW
#define NCHUNK 64    // conv K chunks of 64 (4 ci each)

// ---------------- scratch (static device arrays; no allocation) -------------
__device__ unsigned g_acth[(size_t)BB * FLAT2];   // act fp16x2, [b][(l*64+co)/2]
__device__ unsigned g_w12h[H2 * FLAT2];           // W12 fp16x2, [j][(l*64+co)/2]
__device__ float    g_b12[H2];
__device__ float    g_cb[C_OUT];
__device__ unsigned g_wh[C_OUT * (KTOT / 2)];     // conv weights fp16x2, [co][K/2]
__device__ unsigned g_f1h[(size_t)FLAT * H12];    // fc1^T fp16x2, [f][h/2]
__device__ unsigned g_f2h[H2 * H12];              // fc2 fp16x2, [j][h/2]

// ---------------- PTX helpers ----------------------------------------------
__device__ __forceinline__ uint32_t smem_u32(const void* p) {
    uint32_t a;
    asm("{ .reg .u64 t; cvta.to.shared.u64 t, %1; cvt.u32.u64 %0, t; }"
        : "=r"(a) : "l"(p));
    return a;
}
__device__ __forceinline__ uint32_t f16pair(float lo, float hi) {
    uint32_t r;
    asm("cvt.rn.f16x2.f32 %0, %1, %2;" : "=r"(r) : "f"(hi), "f"(lo));
    return r;
}
__device__ __forceinline__ unsigned short f16one(float v) {
    unsigned short r;
    asm("cvt.rn.f16.f32 %0, %1;" : "=h"(r) : "f"(v));
    return r;
}
__device__ __forceinline__ uint32_t lds32(uint32_t addr) {
    uint32_t v;
    asm volatile("ld.shared.b32 %0, [%1];" : "=r"(v) : "r"(addr));
    return v;
}
__device__ __forceinline__ void sts64(uint32_t addr, uint32_t v0, uint32_t v1) {
    asm volatile("st.shared.v2.b32 [%0], {%1, %2};" :: "r"(addr), "r"(v0), "r"(v1));
}
__device__ __forceinline__ void sts128(uint32_t addr, uint4 v) {
    asm volatile("st.shared.v4.b32 [%0], {%1, %2, %3, %4};"
                 :: "r"(addr), "r"(v.x), "r"(v.y), "r"(v.z), "r"(v.w));
}
__device__ __forceinline__ void ldsm4(uint32_t* r, uint32_t addr) {
    asm volatile("ldmatrix.sync.aligned.m8n8.x4.shared.b16 {%0,%1,%2,%3}, [%4];"
                 : "=r"(r[0]), "=r"(r[1]), "=r"(r[2]), "=r"(r[3]) : "r"(addr));
}
__device__ __forceinline__ void hmma(float* d, uint32_t a0, uint32_t a1,
                                     uint32_t a2, uint32_t a3,
                                     uint32_t b0, uint32_t b1) {
    asm volatile("mma.sync.aligned.m16n8k16.row.col.f32.f16.f16.f32 "
                 "{%0,%1,%2,%3}, {%4,%5,%6,%7}, {%8,%9}, {%0,%1,%2,%3};"
                 : "+f"(d[0]), "+f"(d[1]), "+f"(d[2]), "+f"(d[3])
                 : "r"(a0), "r"(a1), "r"(a2), "r"(a3), "r"(b0), "r"(b1));
}
#define CP_ASYNC16(dst, src) \
    asm volatile("cp.async.cg.shared.global [%0], [%1], 16;" \
                 :: "r"(dst), "l"(src) : "memory")
#define CP_COMMIT() asm volatile("cp.async.commit_group;" ::: "memory")
#define CP_WAIT1()  asm volatile("cp.async.wait_group 1;" ::: "memory")

// ---------------------------------------------------------------------------
// prep_all: one launch for all weight preprocessing.
// ---------------------------------------------------------------------------
__global__ void __launch_bounds__(256) prep_all_kernel(
        const float* __restrict__ conv_w, const float* __restrict__ conv_b,
        const float* __restrict__ gamma,  const float* __restrict__ beta,
        const float* __restrict__ mean,   const float* __restrict__ var,
        const float* __restrict__ fc1_b,  const float* __restrict__ fc2_w,
        const float* __restrict__ fc2_b) {
    int bid = blockIdx.x, t = threadIdx.x;
    if (bid < 512) {
        int idx = bid * 256 + t;              // exactly C_OUT*(KTOT/2)
        int co = idx >> 11;
        int kg = (idx & 2047) * 2;
        int ci = kg >> 4, k = kg & 15;
        float inv = gamma[co] * rsqrtf(var[co] + 1e-5f);
        const float* src = conv_w + ((size_t)co * C_IN + ci) * KW + k;
        g_wh[idx] = f16pair(src[0] * inv, src[1] * inv);
    } else if (bid < 640) {
        int idx = (bid - 512) * 256 + t;      // exactly H2*H12
        g_f2h[idx] = f16pair(fc2_w[2 * idx], fc2_w[2 * idx + 1]);
    } else {
        if (t < H2) {
            float s = fc2_b[t];
            for (int h = 0; h < H1; h++) s = fmaf(fc2_w[t * H1 + h], fc1_b[h], s);
            g_b12[t] = s;
        } else if (t < H2 + C_OUT) {
            int co = t - H2;
            float inv = gamma[co] * rsqrtf(var[co] + 1e-5f);
            g_cb[co] = (conv_b[co] - mean[co]) * inv + beta[co];
        }
    }
}

// ---------------------------------------------------------------------------
// fc1 transpose + cvt: [h=512][f=3904] fp32 -> g_f1h [f][h/2] fp16x2.
// ---------------------------------------------------------------------------
__global__ void __launch_bounds__(256) f1t_kernel(const float* __restrict__ fc1_w) {
    __shared__ float s[64][33];
    int t  = threadIdx.x;
    int f0 = blockIdx.x * 32;
    int h0 = blockIdx.y * 64;
#pragma unroll
    for (int it = 0; it < 8; it++) {
        int idx = it * 256 + t;
        int hh = idx >> 5, ff = idx & 31;
        s[hh][ff] = fc1_w[(size_t)(h0 + hh) * FLAT + f0 + ff];
    }
    __syncthreads();
    int hb2 = blockIdx.y * 32;
#pragma unroll
    for (int it = 0; it < 4; it++) {
        int idx = it * 256 + t;
        int ff = idx >> 5, pi = idx & 31;
        g_f1h[(size_t)(f0 + ff) * H12 + hb2 + pi] =
            f16pair(s[2 * pi][ff], s[2 * pi + 1][ff]);
    }
}

// ---------------------------------------------------------------------------
// W12 = fc2 @ fc1 via mma.sync. M=128 j, N=32 f per block (grid 122), K=512.
// ---------------------------------------------------------------------------
__global__ void __launch_bounds__(256) w12mma_kernel() {
    __shared__ uint32_t asm_[H2 * 32];
    __shared__ uint32_t bsm_[32 * 32];

    int t = threadIdx.x, w = t >> 5, lane = t & 31;
    int mw = w;
    uint32_t as_addr = smem_u32(asm_);
    uint32_t bs_addr = smem_u32(bsm_);
    int f0 = blockIdx.x * 32;

    float acc[4][4];
#pragma unroll
    for (int nt = 0; nt < 4; nt++)
#pragma unroll
        for (int r = 0; r < 4; r++) acc[nt][r] = 0.f;

    int sub = lane >> 3, r8 = lane & 7;
    int arow = mw * 16 + (sub & 1) * 8 + r8;
    uint32_t akb   = (uint32_t)((sub >> 1) * 16);
    uint32_t abase = as_addr + (uint32_t)(arow * 128);
    uint32_t aswz  = (uint32_t)(r8 << 4);

    int btile = lane >> 3, brow = lane & 7;
    uint32_t bbase[2];
    uint32_t bkb  = (uint32_t)((btile & 1) * 16);
    uint32_t bswz = (uint32_t)(brow << 4);
#pragma unroll
    for (int p = 0; p < 2; p++) {
        int floc = (2 * p + (btile >> 1)) * 8 + brow;
        bbase[p] = bs_addr + (uint32_t)(floc * 128);
    }

    int wj = t >> 1, wh = t & 1;
    char* arowp = (char*)asm_ + wj * 128;
    uint32_t awz = (uint32_t)((wj & 7) << 4);
    int am = t >> 3, akg = t & 7;
    uint32_t bst = bs_addr + (uint32_t)(am * 128) +
                   (((uint32_t)(akg * 16)) ^ ((uint32_t)((am & 7) << 4)));

#pragma unroll 1
    for (int cc = 0; cc < 8; cc++) {
        __syncthreads();
        {
            const uint4* src = (const uint4*)(g_f2h + (size_t)wj * H12 + cc * 32 + wh * 16);
#pragma unroll
            for (int qq = 0; qq < 4; qq++) {
                uint4 v = src[qq];
                *(uint4*)(arowp + (((uint32_t)(wh * 64 + qq * 16)) ^ awz)) = v;
            }
        }
        {
            uint4 v = *(const uint4*)(g_f1h + (size_t)(f0 + am) * H12 + cc * 32 + akg * 4);
            *(uint4*)((char*)bsm_ + (bst - bs_addr)) = v;
        }
        __syncthreads();

#pragma unroll
        for (int ks = 0; ks < 4; ks++) {
            uint32_t af[4];
            ldsm4(af, abase + (((uint32_t)(ks * 32) + akb) ^ aswz));
            uint32_t bf[8];
#pragma unroll
            for (int p = 0; p < 2; p++)
                ldsm4(&bf[4 * p], bbase[p] + (((uint32_t)(ks * 32) + bkb) ^ bswz));
#pragma unroll
            for (int nt = 0; nt < 4; nt++) {
                int bi = 4 * (nt >> 1) + 2 * (nt & 1);
                hmma(acc[nt], af[0], af[1], af[2], af[3], bf[bi], bf[bi + 1]);
            }
        }
    }

    unsigned short* dst = (unsigned short*)g_w12h;
    int r = lane >> 2, c = lane & 3;
#pragma unroll
    for (int nt = 0; nt < 4; nt++) {
#pragma unroll
        for (int e = 0; e < 4; e++) {
            int f = f0 + nt * 8 + 2 * c + (e & 1);
            int j = mw * 16 + r + (e >> 1) * 8;
            int co = f / L_OUT;
            int l  = f - co * L_OUT;
            dst[(size_t)j * FLAT + l * 64 + co] = f16one(acc[nt][e]);
        }
    }
}

// ---------------------------------------------------------------------------
// Conv + BN + ReLU via mma.sync (exact R12 structure — best measured).
// ---------------------------------------------------------------------------
__global__ void __launch_bounds__(256, 2) conv_mma_kernel(const float* __restrict__ x) {
    __shared__ unsigned xh[2][16 * 128];     // fp16x2 x, 2 x 8KB
    __shared__ uint32_t bsm[2][C_OUT * 32];  // fp16x2 weights swizzled, 2 x 8KB

    int t = threadIdx.x, w = t >> 5, lane = t & 31;
    int q = w >> 1, half = w & 1;
    uint32_t xh_addr = smem_u32(xh);
    uint32_t bs_addr = smem_u32(bsm);

    float acc[2][8][4];
#pragma unroll
    for (int mt = 0; mt < 2; mt++)
#pragma unroll
        for (int nt = 0; nt < 8; nt++)
#pragma unroll
            for (int r = 0; r < 4; r++) acc[mt][nt][r] = 0.f;

    int btile = lane >> 3, brow = lane & 7;
    uint32_t bbase[4], bkb[4], bsw[4];
#pragma unroll
    for (int p = 0; p < 4; p++) {
        int co = (2 * p + (btile >> 1)) * 8 + brow;
        bbase[p] = (uint32_t)(co * 128);
        bkb[p]   = (uint32_t)((btile & 1) * 16);
        bsw[p]   = (uint32_t)((co & 7) << 4);
    }

    int c = lane & 3, rq = lane >> 2;
    int lbase = half * 32;
    uint32_t aoff = (uint32_t)(8 * (lbase + rq) + 4 * c);

    int xr = t >> 4, lane16 = t & 15;
    int xq = xr >> 2, xci = xr & 3;
    const float4* xsrc = (const float4*)x
        + ((size_t)(blockIdx.x * 4 + xq) * (C_IN * L_IN) + xci * L_IN) / 4 + lane16;
    uint32_t xsts = xh_addr + (uint32_t)(xr * 512 + lane16 * 8);

    int brw = t >> 3;
    int bg  = t & 7;
    uint32_t bd0 = bs_addr + (uint32_t)(brw * 128) + (((uint32_t)(bg * 16)) ^ ((uint32_t)((brw & 7) << 4)));
    uint32_t bd1 = bs_addr + (uint32_t)((brw + 32) * 128) + (((uint32_t)(bg * 16)) ^ ((uint32_t)(((brw + 32) & 7) << 4)));
    const char* bsrc0 = (const char*)g_wh + (size_t)brw * 8192 + bg * 16;
    const char* bsrc1 = bsrc0 + (size_t)32 * 8192;

    // preload chunk 0
    float4 rx0 = xsrc[0], rx1 = xsrc[16], rx2 = xsrc[32], rx3 = xsrc[48];
    CP_ASYNC16(bd0, bsrc0);
    CP_ASYNC16(bd1, bsrc1);
    CP_COMMIT();

#pragma unroll 1
    for (int cc = 0; cc < NCHUNK; cc++) {
        __syncthreads();                       // prior compute done; buffers free
        {
            uint32_t xb = xsts + (uint32_t)((cc & 1) * 8192);
            sts64(xb,        f16pair(rx0.x, rx0.y), f16pair(rx0.z, rx0.w));
            sts64(xb + 128,  f16pair(rx1.x, rx1.y), f16pair(rx1.z, rx1.w));
            sts64(xb + 256,  f16pair(rx2.x, rx2.y), f16pair(rx2.z, rx2.w));
            sts64(xb + 384,  f16pair(rx3.x, rx3.y), f16pair(rx3.z, rx3.w));
        }
        if (cc < NCHUNK - 1) {                 // prefetch next chunk
            const float4* nsrc = xsrc + (size_t)(cc + 1) * 256;
            rx0 = nsrc[0]; rx1 = nsrc[16]; rx2 = nsrc[32]; rx3 = nsrc[48];
            uint32_t bb = (uint32_t)(((cc + 1) & 1) * (C_OUT * 32 * 4));
            size_t bo = (size_t)(cc + 1) * 128;
            CP_ASYNC16(bd0 + bb, bsrc0 + bo);
            CP_ASYNC16(bd1 + bb, bsrc1 + bo);
        }
        CP_COMMIT();
        CP_WAIT1();                            // B(cc) landed
        __syncthreads();                       // x stores visible to all warps

        int buf = cc & 1;
        uint32_t bbuf = bs_addr + (uint32_t)(buf * (C_OUT * 32 * 4));
        uint32_t xchunk = xh_addr + (uint32_t)(buf * 8192) + (uint32_t)(q * 4 * 512);

#pragma unroll
        for (int ks = 0; ks < 4; ks++) {
            uint32_t bfr[16];
#pragma unroll
            for (int p = 0; p < 4; p++) {
                uint32_t addr = bbuf + bbase[p] + (((uint32_t)(ks * 32) + bkb[p]) ^ bsw[p]);
                ldsm4(&bfr[4 * p], addr);
            }
            uint32_t xrow = xchunk + (uint32_t)(ks * 512) + aoff;
#pragma unroll
            for (int mt = 0; mt < 2; mt++) {
                uint32_t base = xrow + (uint32_t)(mt * 128);
                uint32_t a0 = lds32(base);
                uint32_t a1 = lds32(base + 64);
                uint32_t a2 = lds32(base + 16);
                uint32_t a3 = lds32(base + 80);
#pragma unroll
                for (int nt = 0; nt < 8; nt++) {
                    int bi = 4 * (nt >> 1) + 2 * (nt & 1);
                    hmma(acc[mt][nt], a0, a1, a2, a3, bfr[bi], bfr[bi + 1]);
                }
            }
        }
    }

    int b = blockIdx.x * 4 + q;
    unsigned* dst = g_acth + (size_t)b * FLAT2;
#pragma unroll
    for (int mt = 0; mt < 2; mt++) {
        int l1 = lbase + mt * 16 + rq;
        int l2 = l1 + 8;
#pragma unroll
        for (int nt = 0; nt < 8; nt++) {
            int co0 = nt * 8 + 2 * c;
            float cb0 = g_cb[co0], cb1 = g_cb[co0 + 1];
            if (l1 < L_OUT) {
                float v0 = acc[mt][nt][0] + cb0;
                float v1 = acc[mt][nt][1] + cb1;
                dst[l1 * 32 + nt * 4 + c] = f16pair(v0 > 0.f ? v0 : 0.f, v1 > 0.f ? v1 : 0.f);
            }
            if (l2 < L_OUT) {
                float v2 = acc[mt][nt][2] + cb0;
                float v3 = acc[mt][nt][3] + cb1;
                dst[l2 * 32 + nt * 4 + c] = f16pair(v2 > 0.f ? v2 : 0.f, v3 > 0.f ? v3 : 0.f);
            }
        }
    }
}

// ---------------------------------------------------------------------------
// feats = act @ W12^T + b12 via mma.sync, fused parabit heads -> out.
// NEW: reg-buffered LDG prefetch (the pattern validated in conv R12):
//   sync -> STS(cc from regs) -> LDG(cc+1 into regs) -> sync -> compute(cc).
// Same addresses/values as before; single smem buffer. M=16 b/block, grid 128.
// ---------------------------------------------------------------------------
__global__ void __launch_bounds__(256) feats_mma_kernel(const float* __restrict__ bit_w,
                                                        const float* __restrict__ bit_b,
                                                        float* __restrict__ out) {
    __shared__ uint32_t as_[16 * 32];
    __shared__ uint32_t ws_[H2 * 32];
    __shared__ float sb12[H2], sbw[H2 * 2], sbb[H2 * 2];

    int t = threadIdx.x, w = t >> 5, lane = t & 31;
    if (t < H2) sb12[t] = g_b12[t];
    if (t < H2 * 2) { sbw[t] = bit_w[t]; sbb[t] = bit_b[t]; }
    uint32_t as_addr = smem_u32(as_);
    uint32_t ws_addr = smem_u32(ws_);

    int b0 = blockIdx.x * 16;

    float acc[2][4];
#pragma unroll
    for (int nt = 0; nt < 2; nt++)
#pragma unroll
        for (int r = 0; r < 4; r++) acc[nt][r] = 0.f;

    int sub = lane >> 3, r8 = lane & 7;
    int arow = (sub & 1) * 8 + r8;
    uint32_t akb   = (uint32_t)((sub >> 1) * 16);
    uint32_t abase = as_addr + (uint32_t)(arow * 128);
    uint32_t aswz  = (uint32_t)(r8 << 4);

    int g = lane >> 3, brow = lane & 7;
    int bj  = w * 16 + (g >> 1) * 8 + brow;
    uint32_t bkb  = (uint32_t)((g & 1) * 16);
    uint32_t bbase = ws_addr + (uint32_t)(bj * 128);
    uint32_t bswz = (uint32_t)(brow << 4);

    // staging addressing (same as R12)
    int am = t >> 3, akg = t & 7;            // A row 0..31 (am<16 valid)
    uint32_t ast = as_addr + (uint32_t)(am * 128) +
                   (((uint32_t)(akg * 16)) ^ ((uint32_t)((am & 7) << 4)));
    const uint4* asrc = (const uint4*)(g_acth + (size_t)(b0 + am) * FLAT2 + akg * 4);

    int wj = t >> 1, wh = t & 1;             // B row 0..127, half
    uint32_t wswz = (uint32_t)((wj & 7) << 4);
    uint32_t wst[4];
#pragma unroll
    for (int qq = 0; qq < 4; qq++)
        wst[qq] = ws_addr + (uint32_t)(wj * 128) +
                  (((uint32_t)(wh * 64 + qq * 16)) ^ wswz);
    const uint4* wsrc = (const uint4*)(g_w12h + (size_t)wj * FLAT2 + wh * 16);

    // preload chunk 0 into registers
    uint4 ra = make_uint4(0, 0, 0, 0);
    if (am < 16) ra = asrc[0];
    uint4 rb0 = wsrc[0], rb1 = wsrc[1], rb2 = wsrc[2], rb3 = wsrc[3];

#pragma unroll 1
    for (int cc = 0; cc < 61; cc++) {
        __syncthreads();                     // previous compute done
        if (am < 16) sts128(ast, ra);
        sts128(wst[0], rb0);
        sts128(wst[1], rb1);
        sts128(wst[2], rb2);
        sts128(wst[3], rb3);
        if (cc < 60) {                       // prefetch next chunk (latency
            size_t off = (size_t)(cc + 1) * 8;   // hidden behind compute)
            if (am < 16) ra = asrc[off];
            rb0 = wsrc[off];
            rb1 = wsrc[off + 1];
            rb2 = wsrc[off + 2];
            rb3 = wsrc[off + 3];
        }
        __syncthreads();                     // stores visible

#pragma unroll
        for (int ks = 0; ks < 4; ks++) {
            uint32_t af[4];
            ldsm4(af, abase + (((uint32_t)(ks * 32) + akb) ^ aswz));
            uint32_t bf[4];
            ldsm4(bf, bbase + (((uint32_t)(ks * 32) + bkb) ^ bswz));
#pragma unroll
            for (int nt = 0; nt < 2; nt++)
                hmma(acc[nt], af[0], af[1], af[2], af[3], bf[2 * nt], bf[2 * nt + 1]);
        }
    }

    int r = lane >> 2, c = lane & 3;
#pragma unroll
    for (int nt = 0; nt < 2; nt++) {
        int j0 = w * 16 + nt * 8 + 2 * c;
        float bj0 = sb12[j0], bj1 = sb12[j0 + 1];
        float bw00 = sbw[j0 * 2], bw01 = sbw[j0 * 2 + 1];
        float bw10 = sbw[j0 * 2 + 2], bw11 = sbw[j0 * 2 + 3];
        float bb00 = sbb[j0 * 2], bb01 = sbb[j0 * 2 + 1];
        float bb10 = sbb[j0 * 2 + 2], bb11 = sbb[j0 * 2 + 3];
        {
            int b = b0 + r;
            float f0 = acc[nt][0] + bj0;
            float f1 = acc[nt][1] + bj1;
            float4 o = make_float4(fmaf(f0, bw00, bb00), fmaf(f0, bw01, bb01),
                                   fmaf(f1, bw10, bb10), fmaf(f1, bw11, bb11));
            *(float4*)(out + ((size_t)b * H2 + j0) * 2) = o;
        }
        {
            int b = b0 + r + 8;
            float f2 = acc[nt][2] + bj0;
            float f3 = acc[nt][3] + bj1;
            float4 o = make_float4(fmaf(f2, bw00, bb00), fmaf(f2, bw01, bb01),
                                   fmaf(f3, bw10, bb10), fmaf(f3, bw11, bb11));
            *(float4*)(out + ((size_t)b * H2 + j0) * 2) = o;
        }
    }
}

// ---------------------------------------------------------------------------
extern "C" void kernel_launch(void* const* d_in, const int* in_sizes, int n_in,
                              void* d_out, int out_size) {
    const float* x      = (const float*)d_in[0];
    const float* conv_w = (const float*)d_in[1];
    const float* conv_b = (const float*)d_in[2];
    const float* gamma  = (const float*)d_in[3];
    const float* beta   = (const float*)d_in[4];
    const float* mean   = (const float*)d_in[5];
    const float* var    = (const float*)d_in[6];
    const float* fc1_w  = (const float*)d_in[7];
    const float* fc1_b  = (const float*)d_in[8];
    const float* fc2_w  = (const float*)d_in[9];
    const float* fc2_b  = (const float*)d_in[10];
    const float* bit_w  = (const float*)d_in[11];
    const float* bit_b  = (const float*)d_in[12];
    float* out = (float*)d_out;

    static cudaStream_t s2 = nullptr;
    static cudaEvent_t evFork = nullptr, evJoin = nullptr;
    if (!s2) {
        cudaStreamCreateWithFlags(&s2, cudaStreamNonBlocking);
        cudaEventCreateWithFlags(&evFork, cudaEventDisableTiming);
        cudaEventCreateWithFlags(&evJoin, cudaEventDisableTiming);
    }

    // R12 topology: main stream prep_all -> conv -> feats;
    // s2: f1t -> w12mma (parallel to conv).
    prep_all_kernel<<<641, 256>>>(conv_w, conv_b, gamma, beta, mean, var,
                                  fc1_b, fc2_w, fc2_b);
    cudaEventRecord(evFork, 0);
    cudaStreamWaitEvent(s2, evFork, 0);
    f1t_kernel<<<dim3(FLAT / 32, 8), 256, 0, s2>>>(fc1_w);
    w12mma_kernel<<<FLAT / 32, 256, 0, s2>>>();
    cudaEventRecord(evJoin, s2);

    conv_mma_kernel<<<BB / 4, 256>>>(x);
    cudaStreamWaitEvent((cudaStream_t)0, evJoin, 0);
    feats_mma_kernel<<<BB / 16, 256>>>(bit_w, bit_b, out);
}

// round 17
// speedup vs baseline: 1.6644x; 1.0696x over previous
#include <cuda_runtime.h>
#include <cstdint>

#define BB 2048
#define C_IN 256
#define L_IN 256
#define C_OUT 64
#define KW 16
#define L_OUT 61
#define FLAT 3904    // 64*61
#define FLAT2 1952   // FLAT/2 (f16x2 pairs)
#define H1 512
#define H12 256      // H1/2 pairs
#define H2 128
#define KTOT 4096    // C_IN*KW
#define NCHUNK 64    // conv K chunks of 64 (4 ci each)

// ---------------- scratch (static device arrays; no allocation) -------------
__device__ unsigned g_acth[(size_t)BB * FLAT2];   // act fp16x2, [b][(l*64+co)/2]
__device__ unsigned g_w12h[H2 * FLAT2];           // W12 fp16x2, [j][(l*64+co)/2]
__device__ float    g_b12[H2];
__device__ float    g_cb[C_OUT];
__device__ unsigned g_wh[C_OUT * (KTOT / 2)];     // conv weights fp16x2, [co][K/2]
__device__ unsigned g_f1h[(size_t)FLAT * H12];    // fc1^T fp16x2, [f][h/2]
__device__ unsigned g_f2h[H2 * H12];              // fc2 fp16x2, [j][h/2]

// ---------------- PTX helpers ----------------------------------------------
__device__ __forceinline__ uint32_t smem_u32(const void* p) {
    uint32_t a;
    asm("{ .reg .u64 t; cvta.to.shared.u64 t, %1; cvt.u32.u64 %0, t; }"
        : "=r"(a) : "l"(p));
    return a;
}
__device__ __forceinline__ uint32_t f16pair(float lo, float hi) {
    uint32_t r;
    asm("cvt.rn.f16x2.f32 %0, %1, %2;" : "=r"(r) : "f"(hi), "f"(lo));
    return r;
}
__device__ __forceinline__ unsigned short f16one(float v) {
    unsigned short r;
    asm("cvt.rn.f16.f32 %0, %1;" : "=h"(r) : "f"(v));
    return r;
}
__device__ __forceinline__ uint32_t lds32(uint32_t addr) {
    uint32_t v;
    asm volatile("ld.shared.b32 %0, [%1];" : "=r"(v) : "r"(addr));
    return v;
}
__device__ __forceinline__ void sts64(uint32_t addr, uint32_t v0, uint32_t v1) {
    asm volatile("st.shared.v2.b32 [%0], {%1, %2};" :: "r"(addr), "r"(v0), "r"(v1));
}
__device__ __forceinline__ void sts128(uint32_t addr, uint4 v) {
    asm volatile("st.shared.v4.b32 [%0], {%1, %2, %3, %4};"
                 :: "r"(addr), "r"(v.x), "r"(v.y), "r"(v.z), "r"(v.w));
}
__device__ __forceinline__ void ldsm4(uint32_t* r, uint32_t addr) {
    asm volatile("ldmatrix.sync.aligned.m8n8.x4.shared.b16 {%0,%1,%2,%3}, [%4];"
                 : "=r"(r[0]), "=r"(r[1]), "=r"(r[2]), "=r"(r[3]) : "r"(addr));
}
__device__ __forceinline__ void hmma(float* d, uint32_t a0, uint32_t a1,
                                     uint32_t a2, uint32_t a3,
                                     uint32_t b0, uint32_t b1) {
    asm volatile("mma.sync.aligned.m16n8k16.row.col.f32.f16.f16.f32 "
                 "{%0,%1,%2,%3}, {%4,%5,%6,%7}, {%8,%9}, {%0,%1,%2,%3};"
                 : "+f"(d[0]), "+f"(d[1]), "+f"(d[2]), "+f"(d[3])
                 : "r"(a0), "r"(a1), "r"(a2), "r"(a3), "r"(b0), "r"(b1));
}
#define CP_ASYNC16(dst, src) \
    asm volatile("cp.async.cg.shared.global [%0], [%1], 16;" \
                 :: "r"(dst), "l"(src) : "memory")
#define CP_COMMIT() asm volatile("cp.async.commit_group;" ::: "memory")
#define CP_WAIT1()  asm volatile("cp.async.wait_group 1;" ::: "memory")

// ---------------------------------------------------------------------------
// prep_conv: conv-weight fold+cvt (bid<512) and folded conv bias (bid 512).
// Exactly what the conv kernel consumes — nothing else on conv's path.
// ---------------------------------------------------------------------------
__global__ void __launch_bounds__(256) prep_conv_kernel(
        const float* __restrict__ conv_w, const float* __restrict__ conv_b,
        const float* __restrict__ gamma,  const float* __restrict__ beta,
        const float* __restrict__ mean,   const float* __restrict__ var) {
    int bid = blockIdx.x, t = threadIdx.x;
    if (bid < 512) {
        int idx = bid * 256 + t;              // exactly C_OUT*(KTOT/2)
        int co = idx >> 11;
        int kg = (idx & 2047) * 2;
        int ci = kg >> 4, k = kg & 15;
        float inv = gamma[co] * rsqrtf(var[co] + 1e-5f);
        const float* src = conv_w + ((size_t)co * C_IN + ci) * KW + k;
        g_wh[idx] = f16pair(src[0] * inv, src[1] * inv);
    } else if (t < C_OUT) {
        float inv = gamma[t] * rsqrtf(var[t] + 1e-5f);
        g_cb[t] = (conv_b[t] - mean[t]) * inv + beta[t];
    }
}

// ---------------------------------------------------------------------------
// prep_fc: bid<128 -> f2h cvt; bid in [128,256) -> b12[j] via block reduction
// (parallel, coalesced — replaces the 512-deep serial chain).
// ---------------------------------------------------------------------------
__global__ void __launch_bounds__(256) prep_fc_kernel(
        const float* __restrict__ fc1_b, const float* __restrict__ fc2_w,
        const float* __restrict__ fc2_b) {
    int bid = blockIdx.x, t = threadIdx.x;
    if (bid < 128) {
        int idx = bid * 256 + t;              // exactly H2*H12
        g_f2h[idx] = f16pair(fc2_w[2 * idx], fc2_w[2 * idx + 1]);
    } else {
        int j = bid - 128;
        __shared__ float red[256];
        const float* wrow = fc2_w + (size_t)j * H1;
        float s = wrow[t] * fc1_b[t] + wrow[t + 256] * fc1_b[t + 256];
        red[t] = s;
        __syncthreads();
#pragma unroll
        for (int st = 128; st > 0; st >>= 1) {
            if (t < st) red[t] += red[t + st];
            __syncthreads();
        }
        if (t == 0) g_b12[j] = red[0] + fc2_b[j];
    }
}

// ---------------------------------------------------------------------------
// fc1 transpose + cvt: [h=512][f=3904] fp32 -> g_f1h [f][h/2] fp16x2.
// ---------------------------------------------------------------------------
__global__ void __launch_bounds__(256) f1t_kernel(const float* __restrict__ fc1_w) {
    __shared__ float s[64][33];
    int t  = threadIdx.x;
    int f0 = blockIdx.x * 32;
    int h0 = blockIdx.y * 64;
#pragma unroll
    for (int it = 0; it < 8; it++) {
        int idx = it * 256 + t;
        int hh = idx >> 5, ff = idx & 31;
        s[hh][ff] = fc1_w[(size_t)(h0 + hh) * FLAT + f0 + ff];
    }
    __syncthreads();
    int hb2 = blockIdx.y * 32;
#pragma unroll
    for (int it = 0; it < 4; it++) {
        int idx = it * 256 + t;
        int ff = idx >> 5, pi = idx & 31;
        g_f1h[(size_t)(f0 + ff) * H12 + hb2 + pi] =
            f16pair(s[2 * pi][ff], s[2 * pi + 1][ff]);
    }
}

// ---------------------------------------------------------------------------
// W12 = fc2 @ fc1 via mma.sync. M=128 j, N=32 f per block (grid 122), K=512.
// ---------------------------------------------------------------------------
__global__ void __launch_bounds__(256) w12mma_kernel() {
    __shared__ uint32_t asm_[H2 * 32];
    __shared__ uint32_t bsm_[32 * 32];

    int t = threadIdx.x, w = t >> 5, lane = t & 31;
    int mw = w;
    uint32_t as_addr = smem_u32(asm_);
    uint32_t bs_addr = smem_u32(bsm_);
    int f0 = blockIdx.x * 32;

    float acc[4][4];
#pragma unroll
    for (int nt = 0; nt < 4; nt++)
#pragma unroll
        for (int r = 0; r < 4; r++) acc[nt][r] = 0.f;

    int sub = lane >> 3, r8 = lane & 7;
    int arow = mw * 16 + (sub & 1) * 8 + r8;
    uint32_t akb   = (uint32_t)((sub >> 1) * 16);
    uint32_t abase = as_addr + (uint32_t)(arow * 128);
    uint32_t aswz  = (uint32_t)(r8 << 4);

    int btile = lane >> 3, brow = lane & 7;
    uint32_t bbase[2];
    uint32_t bkb  = (uint32_t)((btile & 1) * 16);
    uint32_t bswz = (uint32_t)(brow << 4);
#pragma unroll
    for (int p = 0; p < 2; p++) {
        int floc = (2 * p + (btile >> 1)) * 8 + brow;
        bbase[p] = bs_addr + (uint32_t)(floc * 128);
    }

    int wj = t >> 1, wh = t & 1;
    char* arowp = (char*)asm_ + wj * 128;
    uint32_t awz = (uint32_t)((wj & 7) << 4);
    int am = t >> 3, akg = t & 7;
    uint32_t bst = bs_addr + (uint32_t)(am * 128) +
                   (((uint32_t)(akg * 16)) ^ ((uint32_t)((am & 7) << 4)));

#pragma unroll 1
    for (int cc = 0; cc < 8; cc++) {
        __syncthreads();
        {
            const uint4* src = (const uint4*)(g_f2h + (size_t)wj * H12 + cc * 32 + wh * 16);
#pragma unroll
            for (int qq = 0; qq < 4; qq++) {
                uint4 v = src[qq];
                *(uint4*)(arowp + (((uint32_t)(wh * 64 + qq * 16)) ^ awz)) = v;
            }
        }
        {
            uint4 v = *(const uint4*)(g_f1h + (size_t)(f0 + am) * H12 + cc * 32 + akg * 4);
            *(uint4*)((char*)bsm_ + (bst - bs_addr)) = v;
        }
        __syncthreads();

#pragma unroll
        for (int ks = 0; ks < 4; ks++) {
            uint32_t af[4];
            ldsm4(af, abase + (((uint32_t)(ks * 32) + akb) ^ aswz));
            uint32_t bf[8];
#pragma unroll
            for (int p = 0; p < 2; p++)
                ldsm4(&bf[4 * p], bbase[p] + (((uint32_t)(ks * 32) + bkb) ^ bswz));
#pragma unroll
            for (int nt = 0; nt < 4; nt++) {
                int bi = 4 * (nt >> 1) + 2 * (nt & 1);
                hmma(acc[nt], af[0], af[1], af[2], af[3], bf[bi], bf[bi + 1]);
            }
        }
    }

    unsigned short* dst = (unsigned short*)g_w12h;
    int r = lane >> 2, c = lane & 3;
#pragma unroll
    for (int nt = 0; nt < 4; nt++) {
#pragma unroll
        for (int e = 0; e < 4; e++) {
            int f = f0 + nt * 8 + 2 * c + (e & 1);
            int j = mw * 16 + r + (e >> 1) * 8;
            int co = f / L_OUT;
            int l  = f - co * L_OUT;
            dst[(size_t)j * FLAT + l * 64 + co] = f16one(acc[nt][e]);
        }
    }
}

// ---------------------------------------------------------------------------
// Conv + BN + ReLU via mma.sync (exact R12/R16 structure — best measured).
// ---------------------------------------------------------------------------
__global__ void __launch_bounds__(256, 2) conv_mma_kernel(const float* __restrict__ x) {
    __shared__ unsigned xh[2][16 * 128];     // fp16x2 x, 2 x 8KB
    __shared__ uint32_t bsm[2][C_OUT * 32];  // fp16x2 weights swizzled, 2 x 8KB

    int t = threadIdx.x, w = t >> 5, lane = t & 31;
    int q = w >> 1, half = w & 1;
    uint32_t xh_addr = smem_u32(xh);
    uint32_t bs_addr = smem_u32(bsm);

    float acc[2][8][4];
#pragma unroll
    for (int mt = 0; mt < 2; mt++)
#pragma unroll
        for (int nt = 0; nt < 8; nt++)
#pragma unroll
            for (int r = 0; r < 4; r++) acc[mt][nt][r] = 0.f;

    int btile = lane >> 3, brow = lane & 7;
    uint32_t bbase[4], bkb[4], bsw[4];
#pragma unroll
    for (int p = 0; p < 4; p++) {
        int co = (2 * p + (btile >> 1)) * 8 + brow;
        bbase[p] = (uint32_t)(co * 128);
        bkb[p]   = (uint32_t)((btile & 1) * 16);
        bsw[p]   = (uint32_t)((co & 7) << 4);
    }

    int c = lane & 3, rq = lane >> 2;
    int lbase = half * 32;
    uint32_t aoff = (uint32_t)(8 * (lbase + rq) + 4 * c);

    int xr = t >> 4, lane16 = t & 15;
    int xq = xr >> 2, xci = xr & 3;
    const float4* xsrc = (const float4*)x
        + ((size_t)(blockIdx.x * 4 + xq) * (C_IN * L_IN) + xci * L_IN) / 4 + lane16;
    uint32_t xsts = xh_addr + (uint32_t)(xr * 512 + lane16 * 8);

    int brw = t >> 3;
    int bg  = t & 7;
    uint32_t bd0 = bs_addr + (uint32_t)(brw * 128) + (((uint32_t)(bg * 16)) ^ ((uint32_t)((brw & 7) << 4)));
    uint32_t bd1 = bs_addr + (uint32_t)((brw + 32) * 128) + (((uint32_t)(bg * 16)) ^ ((uint32_t)(((brw + 32) & 7) << 4)));
    const char* bsrc0 = (const char*)g_wh + (size_t)brw * 8192 + bg * 16;
    const char* bsrc1 = bsrc0 + (size_t)32 * 8192;

    // preload chunk 0
    float4 rx0 = xsrc[0], rx1 = xsrc[16], rx2 = xsrc[32], rx3 = xsrc[48];
    CP_ASYNC16(bd0, bsrc0);
    CP_ASYNC16(bd1, bsrc1);
    CP_COMMIT();

#pragma unroll 1
    for (int cc = 0; cc < NCHUNK; cc++) {
        __syncthreads();                       // prior compute done; buffers free
        {
            uint32_t xb = xsts + (uint32_t)((cc & 1) * 8192);
            sts64(xb,        f16pair(rx0.x, rx0.y), f16pair(rx0.z, rx0.w));
            sts64(xb + 128,  f16pair(rx1.x, rx1.y), f16pair(rx1.z, rx1.w));
            sts64(xb + 256,  f16pair(rx2.x, rx2.y), f16pair(rx2.z, rx2.w));
            sts64(xb + 384,  f16pair(rx3.x, rx3.y), f16pair(rx3.z, rx3.w));
        }
        if (cc < NCHUNK - 1) {                 // prefetch next chunk
            const float4* nsrc = xsrc + (size_t)(cc + 1) * 256;
            rx0 = nsrc[0]; rx1 = nsrc[16]; rx2 = nsrc[32]; rx3 = nsrc[48];
            uint32_t bb = (uint32_t)(((cc + 1) & 1) * (C_OUT * 32 * 4));
            size_t bo = (size_t)(cc + 1) * 128;
            CP_ASYNC16(bd0 + bb, bsrc0 + bo);
            CP_ASYNC16(bd1 + bb, bsrc1 + bo);
        }
        CP_COMMIT();
        CP_WAIT1();                            // B(cc) landed
        __syncthreads();                       // x stores visible to all warps

        int buf = cc & 1;
        uint32_t bbuf = bs_addr + (uint32_t)(buf * (C_OUT * 32 * 4));
        uint32_t xchunk = xh_addr + (uint32_t)(buf * 8192) + (uint32_t)(q * 4 * 512);

#pragma unroll
        for (int ks = 0; ks < 4; ks++) {
            uint32_t bfr[16];
#pragma unroll
            for (int p = 0; p < 4; p++) {
                uint32_t addr = bbuf + bbase[p] + (((uint32_t)(ks * 32) + bkb[p]) ^ bsw[p]);
                ldsm4(&bfr[4 * p], addr);
            }
            uint32_t xrow = xchunk + (uint32_t)(ks * 512) + aoff;
#pragma unroll
            for (int mt = 0; mt < 2; mt++) {
                uint32_t base = xrow + (uint32_t)(mt * 128);
                uint32_t a0 = lds32(base);
                uint32_t a1 = lds32(base + 64);
                uint32_t a2 = lds32(base + 16);
                uint32_t a3 = lds32(base + 80);
#pragma unroll
                for (int nt = 0; nt < 8; nt++) {
                    int bi = 4 * (nt >> 1) + 2 * (nt & 1);
                    hmma(acc[mt][nt], a0, a1, a2, a3, bfr[bi], bfr[bi + 1]);
                }
            }
        }
    }

    int b = blockIdx.x * 4 + q;
    unsigned* dst = g_acth + (size_t)b * FLAT2;
#pragma unroll
    for (int mt = 0; mt < 2; mt++) {
        int l1 = lbase + mt * 16 + rq;
        int l2 = l1 + 8;
#pragma unroll
        for (int nt = 0; nt < 8; nt++) {
            int co0 = nt * 8 + 2 * c;
            float cb0 = g_cb[co0], cb1 = g_cb[co0 + 1];
            if (l1 < L_OUT) {
                float v0 = acc[mt][nt][0] + cb0;
                float v1 = acc[mt][nt][1] + cb1;
                dst[l1 * 32 + nt * 4 + c] = f16pair(v0 > 0.f ? v0 : 0.f, v1 > 0.f ? v1 : 0.f);
            }
            if (l2 < L_OUT) {
                float v2 = acc[mt][nt][2] + cb0;
                float v3 = acc[mt][nt][3] + cb1;
                dst[l2 * 32 + nt * 4 + c] = f16pair(v2 > 0.f ? v2 : 0.f, v3 > 0.f ? v3 : 0.f);
            }
        }
    }
}

// ---------------------------------------------------------------------------
// feats = act @ W12^T + b12 via mma.sync, fused parabit heads -> out.
// Reg-buffered LDG prefetch (R16 winner, byte-identical).
// ---------------------------------------------------------------------------
__global__ void __launch_bounds__(256) feats_mma_kernel(const float* __restrict__ bit_w,
                                                        const float* __restrict__ bit_b,
                                                        float* __restrict__ out) {
    __shared__ uint32_t as_[16 * 32];
    __shared__ uint32_t ws_[H2 * 32];
    __shared__ float sb12[H2], sbw[H2 * 2], sbb[H2 * 2];

    int t = threadIdx.x, w = t >> 5, lane = t & 31;
    if (t < H2) sb12[t] = g_b12[t];
    if (t < H2 * 2) { sbw[t] = bit_w[t]; sbb[t] = bit_b[t]; }
    uint32_t as_addr = smem_u32(as_);
    uint32_t ws_addr = smem_u32(ws_);

    int b0 = blockIdx.x * 16;

    float acc[2][4];
#pragma unroll
    for (int nt = 0; nt < 2; nt++)
#pragma unroll
        for (int r = 0; r < 4; r++) acc[nt][r] = 0.f;

    int sub = lane >> 3, r8 = lane & 7;
    int arow = (sub & 1) * 8 + r8;
    uint32_t akb   = (uint32_t)((sub >> 1) * 16);
    uint32_t abase = as_addr + (uint32_t)(arow * 128);
    uint32_t aswz  = (uint32_t)(r8 << 4);

    int g = lane >> 3, brow = lane & 7;
    int bj  = w * 16 + (g >> 1) * 8 + brow;
    uint32_t bkb  = (uint32_t)((g & 1) * 16);
    uint32_t bbase = ws_addr + (uint32_t)(bj * 128);
    uint32_t bswz = (uint32_t)(brow << 4);

    int am = t >> 3, akg = t & 7;
    uint32_t ast = as_addr + (uint32_t)(am * 128) +
                   (((uint32_t)(akg * 16)) ^ ((uint32_t)((am & 7) << 4)));
    const uint4* asrc = (const uint4*)(g_acth + (size_t)(b0 + am) * FLAT2 + akg * 4);

    int wj = t >> 1, wh = t & 1;
    uint32_t wswz = (uint32_t)((wj & 7) << 4);
    uint32_t wst[4];
#pragma unroll
    for (int qq = 0; qq < 4; qq++)
        wst[qq] = ws_addr + (uint32_t)(wj * 128) +
                  (((uint32_t)(wh * 64 + qq * 16)) ^ wswz);
    const uint4* wsrc = (const uint4*)(g_w12h + (size_t)wj * FLAT2 + wh * 16);

    uint4 ra = make_uint4(0, 0, 0, 0);
    if (am < 16) ra = asrc[0];
    uint4 rb0 = wsrc[0], rb1 = wsrc[1], rb2 = wsrc[2], rb3 = wsrc[3];

#pragma unroll 1
    for (int cc = 0; cc < 61; cc++) {
        __syncthreads();
        if (am < 16) sts128(ast, ra);
        sts128(wst[0], rb0);
        sts128(wst[1], rb1);
        sts128(wst[2], rb2);
        sts128(wst[3], rb3);
        if (cc < 60) {
            size_t off = (size_t)(cc + 1) * 8;
            if (am < 16) ra = asrc[off];
            rb0 = wsrc[off];
            rb1 = wsrc[off + 1];
            rb2 = wsrc[off + 2];
            rb3 = wsrc[off + 3];
        }
        __syncthreads();

#pragma unroll
        for (int ks = 0; ks < 4; ks++) {
            uint32_t af[4];
            ldsm4(af, abase + (((uint32_t)(ks * 32) + akb) ^ aswz));
            uint32_t bf[4];
            ldsm4(bf, bbase + (((uint32_t)(ks * 32) + bkb) ^ bswz));
#pragma unroll
            for (int nt = 0; nt < 2; nt++)
                hmma(acc[nt], af[0], af[1], af[2], af[3], bf[2 * nt], bf[2 * nt + 1]);
        }
    }

    int r = lane >> 2, c = lane & 3;
#pragma unroll
    for (int nt = 0; nt < 2; nt++) {
        int j0 = w * 16 + nt * 8 + 2 * c;
        float bj0 = sb12[j0], bj1 = sb12[j0 + 1];
        float bw00 = sbw[j0 * 2], bw01 = sbw[j0 * 2 + 1];
        float bw10 = sbw[j0 * 2 + 2], bw11 = sbw[j0 * 2 + 3];
        float bb00 = sbb[j0 * 2], bb01 = sbb[j0 * 2 + 1];
        float bb10 = sbb[j0 * 2 + 2], bb11 = sbb[j0 * 2 + 3];
        {
            int b = b0 + r;
            float f0 = acc[nt][0] + bj0;
            float f1 = acc[nt][1] + bj1;
            float4 o = make_float4(fmaf(f0, bw00, bb00), fmaf(f0, bw01, bb01),
                                   fmaf(f1, bw10, bb10), fmaf(f1, bw11, bb11));
            *(float4*)(out + ((size_t)b * H2 + j0) * 2) = o;
        }
        {
            int b = b0 + r + 8;
            float f2 = acc[nt][2] + bj0;
            float f3 = acc[nt][3] + bj1;
            float4 o = make_float4(fmaf(f2, bw00, bb00), fmaf(f2, bw01, bb01),
                                   fmaf(f3, bw10, bb10), fmaf(f3, bw11, bb11));
            *(float4*)(out + ((size_t)b * H2 + j0) * 2) = o;
        }
    }
}

// ---------------------------------------------------------------------------
extern "C" void kernel_launch(void* const* d_in, const int* in_sizes, int n_in,
                              void* d_out, int out_size) {
    const float* x      = (const float*)d_in[0];
    const float* conv_w = (const float*)d_in[1];
    const float* conv_b = (const float*)d_in[2];
    const float* gamma  = (const float*)d_in[3];
    const float* beta   = (const float*)d_in[4];
    const float* mean   = (const float*)d_in[5];
    const float* var    = (const float*)d_in[6];
    const float* fc1_w  = (const float*)d_in[7];
    const float* fc1_b  = (const float*)d_in[8];
    const float* fc2_w  = (const float*)d_in[9];
    const float* fc2_b  = (const float*)d_in[10];
    const float* bit_w  = (const float*)d_in[11];
    const float* bit_b  = (const float*)d_in[12];
    float* out = (float*)d_out;

    static cudaStream_t s2 = nullptr;
    static cudaEvent_t evFork = nullptr, evJoin = nullptr;
    if (!s2) {
        cudaStreamCreateWithFlags(&s2, cudaStreamNonBlocking);
        cudaEventCreateWithFlags(&evFork, cudaEventDisableTiming);
        cudaEventCreateWithFlags(&evJoin, cudaEventDisableTiming);
    }

    // stream0: prep_conv -> conv -> (wait evJoin) feats
    // s2:      prep_fc -> f1t -> w12mma   (entirely off conv's critical path)
    cudaEventRecord(evFork, 0);
    cudaStreamWaitEvent(s2, evFork, 0);
    prep_fc_kernel<<<256, 256, 0, s2>>>(fc1_b, fc2_w, fc2_b);
    f1t_kernel<<<dim3(FLAT / 32, 8), 256, 0, s2>>>(fc1_w);
    w12mma_kernel<<<FLAT / 32, 256, 0, s2>>>();
    cudaEventRecord(evJoin, s2);

    prep_conv_kernel<<<513, 256>>>(conv_w, conv_b, gamma, beta, mean, var);
    conv_mma_kernel<<<BB / 4, 256>>>(x);
    cudaStreamWaitEvent((cudaStream_t)0, evJoin, 0);
    feats_mma_kernel<<<BB / 16, 256>>>(bit_w, bit_b, out);
}